// round 8
// baseline (speedup 1.0000x reference)
#include <cuda_runtime.h>
#include <cuda_fp16.h>
#include <cstdint>

#define BATCH   4
#define SEQ     8192
#define DIM     512
#define HEADS   8
#define NTOK    32768
#define QKVW    1536
#define SCALE_Q 0.125f
#define MTILES  256
#define PADT    133

// ---------------- scratch ----------------
__device__ __align__(16) __half g_a[(size_t)NTOK * DIM];
__device__ __align__(16) __half g_o[(size_t)NTOK * DIM];
__device__ __align__(16) __half g_wq[(size_t)DIM * QKVW];
__device__ __align__(16) __half g_wo[(size_t)DIM * DIM];
__device__ __align__(16) __half g_k[(size_t)NTOK * 512];   // head-major [b][h][n][64]
__device__ __align__(16) __half g_v[(size_t)NTOK * 512];   // head-major [b][h][n][64]
__device__ float g_q[(size_t)NTOK * 512];                   // exp(q*scale), [token][512]
__device__ float g_ctx[BATCH * HEADS * 64 * 64];
__device__ float g_qsum[BATCH * DIM];

// ---------------- PTX helpers (family-target-safe only) ----------------
__device__ __forceinline__ uint32_t s2u(const void* p) {
    uint32_t a;
    asm("{ .reg .u64 t; cvta.to.shared.u64 t, %1; cvt.u32.u64 %0, t; }" : "=r"(a) : "l"(p));
    return a;
}
#define CP16(d, s)                                                            \
    asm volatile("cp.async.cg.shared.global [%0], [%1], 16;" :: "r"(d), "l"(s) : "memory")
#define CPCOMMIT() asm volatile("cp.async.commit_group;" ::: "memory")
#define CPWAIT1()  asm volatile("cp.async.wait_group 1;" ::: "memory")
#define LDSM_X4(r, a)                                                         \
    asm volatile("ldmatrix.sync.aligned.m8n8.x4.shared.b16 {%0,%1,%2,%3}, [%4];" \
        : "=r"((r)[0]), "=r"((r)[1]), "=r"((r)[2]), "=r"((r)[3]) : "r"(a))
#define LDSM_X2T(r, a)                                                        \
    asm volatile("ldmatrix.sync.aligned.m8n8.x2.trans.shared.b16 {%0,%1}, [%2];" \
        : "=r"((r)[0]), "=r"((r)[1]) : "r"(a))
#define MMA(d, a, b)                                                          \
    asm volatile("mma.sync.aligned.m16n8k16.row.col.f32.f16.f16.f32 "         \
        "{%0,%1,%2,%3},{%4,%5,%6,%7},{%8,%9},{%0,%1,%2,%3};"                  \
        : "+f"((d)[0]), "+f"((d)[1]), "+f"((d)[2]), "+f"((d)[3])              \
        : "r"((a)[0]), "r"((a)[1]), "r"((a)[2]), "r"((a)[3]),                 \
          "r"((b)[0]), "r"((b)[1]))

// ---------------- init ----------------
__global__ void init_kernel() {
    int i = blockIdx.x * 256 + threadIdx.x;
    if (i < BATCH * HEADS * 64 * 64) g_ctx[i] = 0.f;
    if (i < BATCH * DIM) g_qsum[i] = 0.f;
}

// ---------------- LayerNorm + transpose -> row-major fp16 ------------------
__global__ __launch_bounds__(256) void ln_kernel(
    const float* __restrict__ x, const float* __restrict__ lw,
    const float* __restrict__ lb)
{
    extern __shared__ float s[];               // [512][33]
    __shared__ float s_mu[32], s_rs[32];
    int tid = threadIdx.x;
    int token0 = blockIdx.x * 32;
    int b = token0 >> 13;
    int n0 = token0 & (SEQ - 1);
    const float* xb = x + (size_t)b * DIM * SEQ;

    #pragma unroll 4
    for (int i = 0; i < 64; i++) {
        int idx = i * 256 + tid;
        int d = idx >> 5, j = idx & 31;
        s[d * 33 + j] = xb[(size_t)d * SEQ + n0 + j];
    }
    __syncthreads();

    int w = tid >> 5, lane = tid & 31;
    for (int t = 0; t < 4; t++) {
        int j = w * 4 + t;
        float sum = 0.f, sq = 0.f;
        #pragma unroll
        for (int d = lane; d < DIM; d += 32) {
            float v = s[d * 33 + j];
            sum += v; sq += v * v;
        }
        #pragma unroll
        for (int o = 16; o; o >>= 1) {
            sum += __shfl_xor_sync(0xffffffffu, sum, o);
            sq  += __shfl_xor_sync(0xffffffffu, sq, o);
        }
        if (lane == 0) {
            float mu = sum * (1.f / DIM);
            float var = sq * (1.f / DIM) - mu * mu;
            s_mu[j] = mu;
            s_rs[j] = rsqrtf(var + 1e-5f);
        }
    }
    __syncthreads();

    #pragma unroll
    for (int it = 0; it < 8; it++) {
        int idx = it * 256 + tid;
        int g = idx & 63, j = idx >> 6;
        int d0 = g * 8;
        float mu = s_mu[j], rs = s_rs[j];
        union { __half h[8]; uint4 u; } ph;
        #pragma unroll
        for (int i = 0; i < 8; i++) {
            int d = d0 + i;
            float v = (s[d * 33 + j] - mu) * rs * lw[d] + lb[d];
            ph.h[i] = __float2half_rn(v);
        }
        *(uint4*)&g_a[(size_t)(token0 + j) * DIM + d0] = ph.u;
    }
}

// ---------------- weight fp32 -> fp16 ---------------------------------------
__global__ __launch_bounds__(256) void wconv_kernel(
    const float* __restrict__ wq, const float* __restrict__ wo)
{
    int stride = gridDim.x * 256;
    for (int i = blockIdx.x * 256 + threadIdx.x; i < DIM * QKVW; i += stride)
        g_wq[i] = __float2half_rn(wq[i]);
    for (int i = blockIdx.x * 256 + threadIdx.x; i < DIM * DIM; i += stride)
        g_wo[i] = __float2half_rn(wo[i]);
}

// ---------------- fp16 HMMA GEMM: C = A @ B, K=512 --------------------------
// mode 0: qkv. q cols -> g_q exp fp32 + colsums; k/v cols -> g_k/g_v fp16
//         head-major [b][h][n][64].
// mode 1: out[b][dout][n] + bias (transposed store).
#define SLICE 10496              // A 6144 + B 4352
#define STAGE (2 * SLICE)        // 20992
__global__ __launch_bounds__(256, 3) void mma_gemm_kernel(
    const __half* __restrict__ A, const __half* __restrict__ B,
    float* __restrict__ C, const float* __restrict__ bias, int ldb, int mode)
{
    extern __shared__ char smem[];
    uint32_t sb = s2u(smem);
    int tid = threadIdx.x, lane = tid & 31, wid = tid >> 5;
    int m0 = blockIdx.y * 128, n0 = blockIdx.x * 128;
    int wm = (wid >> 2) * 64, wn = (wid & 3) * 32;

    int ar = tid >> 1, ah8 = (tid & 1) * 8;
    int bkr = tid >> 4, bn8 = (tid & 15) * 8;
    const __half* Ag = A + (size_t)(m0 + ar) * DIM + ah8;
    const __half* Bg = B + (size_t)bkr * ldb + n0 + bn8;
    uint32_t dA = sb + ar * 48 + ah8 * 2;
    uint32_t dB = sb + 6144 + bkr * 272 + bn8 * 2;

    uint32_t aAddr[4], bAddr[4];
    #pragma unroll
    for (int mi = 0; mi < 4; mi++)
        aAddr[mi] = sb + (wm + mi * 16 + (lane & 15)) * 48 + (lane >> 4) * 16;
    #pragma unroll
    for (int ni = 0; ni < 4; ni++)
        bAddr[ni] = sb + 6144 + (lane & 15) * 272 + (wn + ni * 8) * 2;

    float d[4][4][4];
    #pragma unroll
    for (int mi = 0; mi < 4; mi++)
        #pragma unroll
        for (int ni = 0; ni < 4; ni++)
            #pragma unroll
            for (int r = 0; r < 4; r++) d[mi][ni][r] = 0.f;

    #pragma unroll
    for (int p = 0; p < 2; p++) {
        #pragma unroll
        for (int s = 0; s < 2; s++) {
            uint32_t so = p * STAGE + s * SLICE;
            int ks = p * 2 + s;
            CP16(dA + so, Ag + ks * 16);
            CP16(dB + so, Bg + (size_t)ks * 16 * ldb);
        }
        CPCOMMIT();
    }

    for (int kk = 0; kk < 16; kk++) {
        CPWAIT1();
        __syncthreads();
        if (kk + 2 < 16) {
            #pragma unroll
            for (int s = 0; s < 2; s++) {
                uint32_t so = ((kk + 2) % 3) * STAGE + s * SLICE;
                int ks = (kk + 2) * 2 + s;
                CP16(dA + so, Ag + ks * 16);
                CP16(dB + so, Bg + (size_t)ks * 16 * ldb);
            }
        }
        CPCOMMIT();

        #pragma unroll
        for (int s = 0; s < 2; s++) {
            uint32_t so = (kk % 3) * STAGE + s * SLICE;
            uint32_t ah[4][4], bh[4][2];
            #pragma unroll
            for (int mi = 0; mi < 4; mi++)
                LDSM_X4(ah[mi], aAddr[mi] + so);
            #pragma unroll
            for (int ni = 0; ni < 4; ni++)
                LDSM_X2T(bh[ni], bAddr[ni] + so);
            #pragma unroll
            for (int mi = 0; mi < 4; mi++)
                #pragma unroll
                for (int ni = 0; ni < 4; ni++)
                    MMA(d[mi][ni], ah[mi], bh[ni]);
        }
    }

    if (mode == 0) {
        int region = n0 >> 9;                  // 0: q, 1: k, 2: v
        if (region == 0) {
            float* qs = (float*)smem;
            __syncthreads();
            if (tid < 128) qs[tid] = 0.f;
            __syncthreads();
            #pragma unroll
            for (int mi = 0; mi < 4; mi++) {
                int r0 = m0 + wm + mi * 16 + (lane >> 2);
                #pragma unroll
                for (int ni = 0; ni < 4; ni++) {
                    int cl = wn + ni * 8 + (lane & 3) * 2;
                    float v0 = __expf(d[mi][ni][0] * SCALE_Q);
                    float v1 = __expf(d[mi][ni][1] * SCALE_Q);
                    float v2 = __expf(d[mi][ni][2] * SCALE_Q);
                    float v3 = __expf(d[mi][ni][3] * SCALE_Q);
                    atomicAdd(&qs[cl],     v0 + v2);
                    atomicAdd(&qs[cl + 1], v1 + v3);
                    *(float2*)&C[(size_t)r0 * 512 + n0 + cl]       = make_float2(v0, v1);
                    *(float2*)&C[(size_t)(r0 + 8) * 512 + n0 + cl] = make_float2(v2, v3);
                }
            }
            __syncthreads();
            if (tid < 128)
                atomicAdd(&g_qsum[(m0 >> 13) * DIM + n0 + tid], qs[tid]);
        } else {
            __half* dstbuf = (region == 1) ? g_k : g_v;
            int colbase = n0 & 511;
            #pragma unroll
            for (int mi = 0; mi < 4; mi++) {
                int r0 = m0 + wm + mi * 16 + (lane >> 2);
                int b = r0 >> 13, n = r0 & (SEQ - 1);
                #pragma unroll
                for (int ni = 0; ni < 4; ni++) {
                    int col = colbase + wn + ni * 8 + (lane & 3) * 2;
                    int h = col >> 6, dd = col & 63;
                    size_t base = ((size_t)(b * HEADS + h) * SEQ + n) * 64 + dd;
                    *(__half2*)&dstbuf[base] =
                        __floats2half2_rn(d[mi][ni][0], d[mi][ni][1]);
                    *(__half2*)&dstbuf[base + 8 * 64] =
                        __floats2half2_rn(d[mi][ni][2], d[mi][ni][3]);
                }
            }
        }
    } else {
        __syncthreads();
        float* st = (float*)smem;             // [128][PADT]
        #pragma unroll
        for (int mi = 0; mi < 4; mi++) {
            int r0 = wm + mi * 16 + (lane >> 2);
            #pragma unroll
            for (int ni = 0; ni < 4; ni++) {
                int c0 = wn + ni * 8 + (lane & 3) * 2;
                st[r0 * PADT + c0]           = d[mi][ni][0];
                st[r0 * PADT + c0 + 1]       = d[mi][ni][1];
                st[(r0 + 8) * PADT + c0]     = d[mi][ni][2];
                st[(r0 + 8) * PADT + c0 + 1] = d[mi][ni][3];
            }
        }
        __syncthreads();
        int b = m0 >> 13, nn0 = m0 & (SEQ - 1);
        float* dst = C + (size_t)b * DIM * SEQ + (size_t)n0 * SEQ + nn0;
        for (int idx = tid; idx < 16384; idx += 256) {
            int r = idx >> 7;
            int c = idx & 127;
            dst[(size_t)r * SEQ + c] = st[c * PADT + r] + bias[n0 + r];
        }
    }
}

// ---------------- k softmax + context accumulation (fp16 head-major in) -----
__global__ __launch_bounds__(256) void ctx_kernel()
{
    __shared__ float kb[16][64];
    __shared__ float vb[16][64];
    int tid = threadIdx.x;
    int h = blockIdx.y;
    int tok0 = blockIdx.x * 512;
    int b = tok0 >> 13;
    int n0 = tok0 & (SEQ - 1);
    int d = tid & 63, eg = tid >> 6;
    int ltt = tid >> 4, ld4 = (tid & 15) * 4;
    float acc[16] = {};

    size_t bh = ((size_t)(b * HEADS + h) * SEQ + n0) * 64;

    for (int t0 = 0; t0 < 512; t0 += 16) {
        size_t off = bh + (size_t)(t0 + ltt) * 64 + ld4;
        uint2 kr = *(const uint2*)&g_k[off];
        uint2 vr = *(const uint2*)&g_v[off];
        __half2 k01 = *(__half2*)&kr.x, k23 = *(__half2*)&kr.y;
        __half2 v01 = *(__half2*)&vr.x, v23 = *(__half2*)&vr.y;
        kb[ltt][ld4]     = __low2float(k01); kb[ltt][ld4 + 1] = __high2float(k01);
        kb[ltt][ld4 + 2] = __low2float(k23); kb[ltt][ld4 + 3] = __high2float(k23);
        vb[ltt][ld4]     = __low2float(v01); vb[ltt][ld4 + 1] = __high2float(v01);
        vb[ltt][ld4 + 2] = __low2float(v23); vb[ltt][ld4 + 3] = __high2float(v23);
        __syncthreads();
        {
            int w = tid >> 5, lane = tid & 31;
            #pragma unroll
            for (int u = 0; u < 2; u++) {
                int tt = w * 2 + u;
                float e0 = __expf(kb[tt][lane]);
                float e1 = __expf(kb[tt][lane + 32]);
                float su = e0 + e1;
                #pragma unroll
                for (int o = 16; o; o >>= 1) su += __shfl_xor_sync(0xffffffffu, su, o);
                float inv = 1.f / su;
                kb[tt][lane] = e0 * inv;
                kb[tt][lane + 32] = e1 * inv;
            }
        }
        __syncthreads();
        #pragma unroll
        for (int tt = 0; tt < 16; tt++) {
            float a = kb[tt][d];
            const float4* vrow = (const float4*)&vb[tt][eg * 16];
            float4 w0 = vrow[0], w1 = vrow[1], w2 = vrow[2], w3 = vrow[3];
            acc[0]  += a * w0.x; acc[1]  += a * w0.y; acc[2]  += a * w0.z; acc[3]  += a * w0.w;
            acc[4]  += a * w1.x; acc[5]  += a * w1.y; acc[6]  += a * w1.z; acc[7]  += a * w1.w;
            acc[8]  += a * w2.x; acc[9]  += a * w2.y; acc[10] += a * w2.z; acc[11] += a * w2.w;
            acc[12] += a * w3.x; acc[13] += a * w3.y; acc[14] += a * w3.z; acc[15] += a * w3.w;
        }
        __syncthreads();
    }
    float* cdst = &g_ctx[((b * HEADS + h) * 64 + d) * 64 + eg * 16];
    #pragma unroll
    for (int c = 0; c < 16; c++) atomicAdd(&cdst[c], acc[c]);
}

// ---------------- o = qexp*rq @ ctx ; write row-major fp16 ------------------
__global__ __launch_bounds__(256) void oproj_kernel()
{
    __shared__ float cs[64][64];
    __shared__ float qt[64][65];
    __shared__ float rq[64];
    int tid = threadIdx.x;
    int h = blockIdx.y;
    int tok0 = blockIdx.x * 64;
    int b = tok0 >> 13;

    const float* csrc = &g_ctx[(b * HEADS + h) * 64 * 64];
    for (int i = tid; i < 4096; i += 256) cs[i >> 6][i & 63] = csrc[i];
    if (tid < 64) rq[tid] = 1.f / g_qsum[b * DIM + h * 64 + tid];
    __syncthreads();

    for (int i = tid; i < 64 * 64; i += 256) {
        int t = i >> 6, dd = i & 63;
        qt[t][dd] = g_q[(size_t)(tok0 + t) * 512 + h * 64 + dd] * rq[dd];
    }
    __syncthreads();

    int tx = tid & 15, ty = tid >> 4;
    float acc[4][4] = {};
    #pragma unroll
    for (int dd = 0; dd < 64; dd++) {
        float a[4], bb[4];
        #pragma unroll
        for (int i = 0; i < 4; i++) a[i] = qt[ty * 4 + i][dd];
        #pragma unroll
        for (int j = 0; j < 4; j++) bb[j] = cs[dd][tx * 4 + j];
        #pragma unroll
        for (int i = 0; i < 4; i++)
            #pragma unroll
            for (int j = 0; j < 4; j++)
                acc[i][j] += a[i] * bb[j];
    }
    #pragma unroll
    for (int i = 0; i < 4; i++) {
        int t = tok0 + ty * 4 + i;
        union { __half h2[4]; uint2 u; } ph;
        #pragma unroll
        for (int j = 0; j < 4; j++)
            ph.h2[j] = __float2half_rn(acc[i][j]);
        *(uint2*)&g_o[(size_t)t * DIM + h * 64 + tx * 4] = ph.u;
    }
}

// ---------------- launch ------------------------------------------------------
extern "C" void kernel_launch(void* const* d_in, const int* in_sizes, int n_in,
                              void* d_out, int out_size)
{
    const float* x     = (const float*)d_in[0];
    const float* ln_w  = (const float*)d_in[1];
    const float* ln_b  = (const float*)d_in[2];
    const float* w_qkv = (const float*)d_in[3];
    const float* w_out = (const float*)d_in[4];
    const float* b_out = (const float*)d_in[5];
    float* out = (float*)d_out;

    __half *p_a, *p_o, *p_wq, *p_wo;
    float* p_q;
    cudaGetSymbolAddress((void**)&p_a, g_a);
    cudaGetSymbolAddress((void**)&p_o, g_o);
    cudaGetSymbolAddress((void**)&p_wq, g_wq);
    cudaGetSymbolAddress((void**)&p_wo, g_wo);
    cudaGetSymbolAddress((void**)&p_q, g_q);

    const int LN_SMEM   = 512 * 33 * 4;
    const int GEMM_SMEM = 128 * PADT * 4;    // 68096 >= 3*STAGE = 62976
    cudaFuncSetAttribute(ln_kernel, cudaFuncAttributeMaxDynamicSharedMemorySize, LN_SMEM);
    cudaFuncSetAttribute(mma_gemm_kernel, cudaFuncAttributeMaxDynamicSharedMemorySize, GEMM_SMEM);

    init_kernel<<<(BATCH * HEADS * 64 * 64 + 255) / 256, 256>>>();
    ln_kernel<<<NTOK / 32, 256, LN_SMEM>>>(x, ln_w, ln_b);
    wconv_kernel<<<1024, 256>>>(w_qkv, w_out);
    mma_gemm_kernel<<<dim3(QKVW / 128, MTILES), 256, GEMM_SMEM>>>(
        p_a, p_wq, p_q, nullptr, QKVW, 0);
    ctx_kernel<<<dim3(NTOK / 512, HEADS), 256>>>();
    oproj_kernel<<<dim3(NTOK / 64, HEADS), 256>>>();
    mma_gemm_kernel<<<dim3(DIM / 128, MTILES), 256, GEMM_SMEM>>>(
        p_o, p_wo, out, b_out, DIM, 1);
}

// round 9
// speedup vs baseline: 1.2291x; 1.2291x over previous
#include <cuda_runtime.h>
#include <cuda_fp16.h>
#include <cstdint>

#define BATCH   4
#define SEQ     8192
#define DIM     512
#define HEADS   8
#define NTOK    32768
#define QKVW    1536
#define SCALE_Q 0.125f
#define MTILES  256
#define PADT    133

// ---------------- scratch ----------------
__device__ __align__(16) __half g_a[(size_t)NTOK * DIM];
__device__ __align__(16) __half g_o[(size_t)NTOK * DIM];
__device__ __align__(16) __half g_wq[(size_t)DIM * QKVW];
__device__ __align__(16) __half g_wo[(size_t)DIM * DIM];
__device__ __align__(16) __half g_k[(size_t)NTOK * 512];   // head-major [b][h][n][64]
__device__ __align__(16) __half g_v[(size_t)NTOK * 512];   // head-major [b][h][n][64]
__device__ float g_q[(size_t)NTOK * 512];                   // exp(q*scale), [token][512]
__device__ float g_ctx[BATCH * HEADS * 64 * 64];
__device__ float g_qsum[BATCH * DIM];

// ---------------- PTX helpers (family-target-safe only) ----------------
__device__ __forceinline__ uint32_t s2u(const void* p) {
    uint32_t a;
    asm("{ .reg .u64 t; cvta.to.shared.u64 t, %1; cvt.u32.u64 %0, t; }" : "=r"(a) : "l"(p));
    return a;
}
#define CP16(d, s)                                                            \
    asm volatile("cp.async.cg.shared.global [%0], [%1], 16;" :: "r"(d), "l"(s) : "memory")
#define CPCOMMIT() asm volatile("cp.async.commit_group;" ::: "memory")
#define CPWAIT1()  asm volatile("cp.async.wait_group 1;" ::: "memory")
#define LDSM_X4(r, a)                                                         \
    asm volatile("ldmatrix.sync.aligned.m8n8.x4.shared.b16 {%0,%1,%2,%3}, [%4];" \
        : "=r"((r)[0]), "=r"((r)[1]), "=r"((r)[2]), "=r"((r)[3]) : "r"(a))
#define LDSM_X2T(r, a)                                                        \
    asm volatile("ldmatrix.sync.aligned.m8n8.x2.trans.shared.b16 {%0,%1}, [%2];" \
        : "=r"((r)[0]), "=r"((r)[1]) : "r"(a))
#define MMA(d, a, b)                                                          \
    asm volatile("mma.sync.aligned.m16n8k16.row.col.f32.f16.f16.f32 "         \
        "{%0,%1,%2,%3},{%4,%5,%6,%7},{%8,%9},{%0,%1,%2,%3};"                  \
        : "+f"((d)[0]), "+f"((d)[1]), "+f"((d)[2]), "+f"((d)[3])              \
        : "r"((a)[0]), "r"((a)[1]), "r"((a)[2]), "r"((a)[3]),                 \
          "r"((b)[0]), "r"((b)[1]))

// ---------------- init ----------------
__global__ void init_kernel() {
    int i = blockIdx.x * 256 + threadIdx.x;
    if (i < BATCH * HEADS * 64 * 64) g_ctx[i] = 0.f;
    if (i < BATCH * DIM) g_qsum[i] = 0.f;
}

// ---------------- LayerNorm + transpose -> row-major fp16 ------------------
__global__ __launch_bounds__(256) void ln_kernel(
    const float* __restrict__ x, const float* __restrict__ lw,
    const float* __restrict__ lb)
{
    extern __shared__ float s[];               // [512][33]
    __shared__ float s_mu[32], s_rs[32];
    int tid = threadIdx.x;
    int token0 = blockIdx.x * 32;
    int b = token0 >> 13;
    int n0 = token0 & (SEQ - 1);
    const float* xb = x + (size_t)b * DIM * SEQ;

    #pragma unroll 4
    for (int i = 0; i < 64; i++) {
        int idx = i * 256 + tid;
        int d = idx >> 5, j = idx & 31;
        s[d * 33 + j] = xb[(size_t)d * SEQ + n0 + j];
    }
    __syncthreads();

    int w = tid >> 5, lane = tid & 31;
    for (int t = 0; t < 4; t++) {
        int j = w * 4 + t;
        float sum = 0.f, sq = 0.f;
        #pragma unroll
        for (int d = lane; d < DIM; d += 32) {
            float v = s[d * 33 + j];
            sum += v; sq += v * v;
        }
        #pragma unroll
        for (int o = 16; o; o >>= 1) {
            sum += __shfl_xor_sync(0xffffffffu, sum, o);
            sq  += __shfl_xor_sync(0xffffffffu, sq, o);
        }
        if (lane == 0) {
            float mu = sum * (1.f / DIM);
            float var = sq * (1.f / DIM) - mu * mu;
            s_mu[j] = mu;
            s_rs[j] = rsqrtf(var + 1e-5f);
        }
    }
    __syncthreads();

    #pragma unroll
    for (int it = 0; it < 8; it++) {
        int idx = it * 256 + tid;
        int g = idx & 63, j = idx >> 6;
        int d0 = g * 8;
        float mu = s_mu[j], rs = s_rs[j];
        union { __half h[8]; uint4 u; } ph;
        #pragma unroll
        for (int i = 0; i < 8; i++) {
            int d = d0 + i;
            float v = (s[d * 33 + j] - mu) * rs * lw[d] + lb[d];
            ph.h[i] = __float2half_rn(v);
        }
        *(uint4*)&g_a[(size_t)(token0 + j) * DIM + d0] = ph.u;
    }
}

// ---------------- weight fp32 -> fp16 ---------------------------------------
__global__ __launch_bounds__(256) void wconv_kernel(
    const float* __restrict__ wq, const float* __restrict__ wo)
{
    int stride = gridDim.x * 256;
    for (int i = blockIdx.x * 256 + threadIdx.x; i < DIM * QKVW; i += stride)
        g_wq[i] = __float2half_rn(wq[i]);
    for (int i = blockIdx.x * 256 + threadIdx.x; i < DIM * DIM; i += stride)
        g_wo[i] = __float2half_rn(wo[i]);
}

// ---------------- fp16 HMMA GEMM: C = A @ B, K=512 --------------------------
// mode 0: qkv. q cols -> g_q exp fp32 + colsums; k/v cols -> g_k/g_v fp16
//         head-major [b][h][n][64].
// mode 1: out[b][dout][n] + bias (transposed store).
#define SLICE 10496              // A 6144 + B 4352
#define STAGE (2 * SLICE)        // 20992
__global__ __launch_bounds__(256) void mma_gemm_kernel(
    const __half* __restrict__ A, const __half* __restrict__ B,
    float* __restrict__ C, const float* __restrict__ bias, int ldb, int mode)
{
    extern __shared__ char smem[];
    uint32_t sb = s2u(smem);
    int tid = threadIdx.x, lane = tid & 31, wid = tid >> 5;
    int m0 = blockIdx.y * 128, n0 = blockIdx.x * 128;
    int wm = (wid >> 2) * 64, wn = (wid & 3) * 32;

    int ar = tid >> 1, ah8 = (tid & 1) * 8;
    int bkr = tid >> 4, bn8 = (tid & 15) * 8;
    const __half* Ag = A + (size_t)(m0 + ar) * DIM + ah8;
    const __half* Bg = B + (size_t)bkr * ldb + n0 + bn8;
    uint32_t dA = sb + ar * 48 + ah8 * 2;
    uint32_t dB = sb + 6144 + bkr * 272 + bn8 * 2;

    uint32_t aAddr[4], bAddr[4];
    #pragma unroll
    for (int mi = 0; mi < 4; mi++)
        aAddr[mi] = sb + (wm + mi * 16 + (lane & 15)) * 48 + (lane >> 4) * 16;
    #pragma unroll
    for (int ni = 0; ni < 4; ni++)
        bAddr[ni] = sb + 6144 + (lane & 15) * 272 + (wn + ni * 8) * 2;

    float d[4][4][4];
    #pragma unroll
    for (int mi = 0; mi < 4; mi++)
        #pragma unroll
        for (int ni = 0; ni < 4; ni++)
            #pragma unroll
            for (int r = 0; r < 4; r++) d[mi][ni][r] = 0.f;

    #pragma unroll
    for (int p = 0; p < 2; p++) {
        #pragma unroll
        for (int s = 0; s < 2; s++) {
            uint32_t so = p * STAGE + s * SLICE;
            int ks = p * 2 + s;
            CP16(dA + so, Ag + ks * 16);
            CP16(dB + so, Bg + (size_t)ks * 16 * ldb);
        }
        CPCOMMIT();
    }

    for (int kk = 0; kk < 16; kk++) {
        CPWAIT1();
        __syncthreads();
        if (kk + 2 < 16) {
            #pragma unroll
            for (int s = 0; s < 2; s++) {
                uint32_t so = ((kk + 2) % 3) * STAGE + s * SLICE;
                int ks = (kk + 2) * 2 + s;
                CP16(dA + so, Ag + ks * 16);
                CP16(dB + so, Bg + (size_t)ks * 16 * ldb);
            }
        }
        CPCOMMIT();

        #pragma unroll
        for (int s = 0; s < 2; s++) {
            uint32_t so = (kk % 3) * STAGE + s * SLICE;
            uint32_t ah[4][4], bh[4][2];
            #pragma unroll
            for (int mi = 0; mi < 4; mi++)
                LDSM_X4(ah[mi], aAddr[mi] + so);
            #pragma unroll
            for (int ni = 0; ni < 4; ni++)
                LDSM_X2T(bh[ni], bAddr[ni] + so);
            #pragma unroll
            for (int mi = 0; mi < 4; mi++)
                #pragma unroll
                for (int ni = 0; ni < 4; ni++)
                    MMA(d[mi][ni], ah[mi], bh[ni]);
        }
    }

    if (mode == 0) {
        int region = n0 >> 9;                  // 0: q, 1: k, 2: v
        if (region == 0) {
            float* qs = (float*)smem;
            __syncthreads();
            if (tid < 128) qs[tid] = 0.f;
            __syncthreads();
            #pragma unroll
            for (int mi = 0; mi < 4; mi++) {
                int r0 = m0 + wm + mi * 16 + (lane >> 2);
                #pragma unroll
                for (int ni = 0; ni < 4; ni++) {
                    int cl = wn + ni * 8 + (lane & 3) * 2;
                    float v0 = __expf(d[mi][ni][0] * SCALE_Q);
                    float v1 = __expf(d[mi][ni][1] * SCALE_Q);
                    float v2 = __expf(d[mi][ni][2] * SCALE_Q);
                    float v3 = __expf(d[mi][ni][3] * SCALE_Q);
                    atomicAdd(&qs[cl],     v0 + v2);
                    atomicAdd(&qs[cl + 1], v1 + v3);
                    *(float2*)&C[(size_t)r0 * 512 + n0 + cl]       = make_float2(v0, v1);
                    *(float2*)&C[(size_t)(r0 + 8) * 512 + n0 + cl] = make_float2(v2, v3);
                }
            }
            __syncthreads();
            if (tid < 128)
                atomicAdd(&g_qsum[(m0 >> 13) * DIM + n0 + tid], qs[tid]);
        } else {
            __half* dstbuf = (region == 1) ? g_k : g_v;
            int colbase = n0 & 511;
            #pragma unroll
            for (int mi = 0; mi < 4; mi++) {
                int r0 = m0 + wm + mi * 16 + (lane >> 2);
                int b = r0 >> 13, n = r0 & (SEQ - 1);
                #pragma unroll
                for (int ni = 0; ni < 4; ni++) {
                    int col = colbase + wn + ni * 8 + (lane & 3) * 2;
                    int h = col >> 6, dd = col & 63;
                    size_t base = ((size_t)(b * HEADS + h) * SEQ + n) * 64 + dd;
                    *(__half2*)&dstbuf[base] =
                        __floats2half2_rn(d[mi][ni][0], d[mi][ni][1]);
                    *(__half2*)&dstbuf[base + 8 * 64] =
                        __floats2half2_rn(d[mi][ni][2], d[mi][ni][3]);
                }
            }
        }
    } else {
        __syncthreads();
        float* st = (float*)smem;             // [128][PADT]
        #pragma unroll
        for (int mi = 0; mi < 4; mi++) {
            int r0 = wm + mi * 16 + (lane >> 2);
            #pragma unroll
            for (int ni = 0; ni < 4; ni++) {
                int c0 = wn + ni * 8 + (lane & 3) * 2;
                st[r0 * PADT + c0]           = d[mi][ni][0];
                st[r0 * PADT + c0 + 1]       = d[mi][ni][1];
                st[(r0 + 8) * PADT + c0]     = d[mi][ni][2];
                st[(r0 + 8) * PADT + c0 + 1] = d[mi][ni][3];
            }
        }
        __syncthreads();
        int b = m0 >> 13, nn0 = m0 & (SEQ - 1);
        float* dst = C + (size_t)b * DIM * SEQ + (size_t)n0 * SEQ + nn0;
        for (int idx = tid; idx < 16384; idx += 256) {
            int r = idx >> 7;
            int c = idx & 127;
            dst[(size_t)r * SEQ + c] = st[c * PADT + r] + bias[n0 + r];
        }
    }
}

// ---------------- k softmax + context accumulation (fp16 head-major in) -----
__global__ __launch_bounds__(256) void ctx_kernel()
{
    __shared__ float kb[16][64];
    __shared__ float vb[16][64];
    int tid = threadIdx.x;
    int h = blockIdx.y;
    int tok0 = blockIdx.x * 512;
    int b = tok0 >> 13;
    int n0 = tok0 & (SEQ - 1);
    int d = tid & 63, eg = tid >> 6;
    int ltt = tid >> 4, ld4 = (tid & 15) * 4;
    float acc[16] = {};

    size_t bh = ((size_t)(b * HEADS + h) * SEQ + n0) * 64;

    for (int t0 = 0; t0 < 512; t0 += 16) {
        size_t off = bh + (size_t)(t0 + ltt) * 64 + ld4;
        uint2 kr = *(const uint2*)&g_k[off];
        uint2 vr = *(const uint2*)&g_v[off];
        __half2 k01 = *(__half2*)&kr.x, k23 = *(__half2*)&kr.y;
        __half2 v01 = *(__half2*)&vr.x, v23 = *(__half2*)&vr.y;
        kb[ltt][ld4]     = __low2float(k01); kb[ltt][ld4 + 1] = __high2float(k01);
        kb[ltt][ld4 + 2] = __low2float(k23); kb[ltt][ld4 + 3] = __high2float(k23);
        vb[ltt][ld4]     = __low2float(v01); vb[ltt][ld4 + 1] = __high2float(v01);
        vb[ltt][ld4 + 2] = __low2float(v23); vb[ltt][ld4 + 3] = __high2float(v23);
        __syncthreads();
        {
            int w = tid >> 5, lane = tid & 31;
            #pragma unroll
            for (int u = 0; u < 2; u++) {
                int tt = w * 2 + u;
                float e0 = __expf(kb[tt][lane]);
                float e1 = __expf(kb[tt][lane + 32]);
                float su = e0 + e1;
                #pragma unroll
                for (int o = 16; o; o >>= 1) su += __shfl_xor_sync(0xffffffffu, su, o);
                float inv = 1.f / su;
                kb[tt][lane] = e0 * inv;
                kb[tt][lane + 32] = e1 * inv;
            }
        }
        __syncthreads();
        #pragma unroll
        for (int tt = 0; tt < 16; tt++) {
            float a = kb[tt][d];
            const float4* vrow = (const float4*)&vb[tt][eg * 16];
            float4 w0 = vrow[0], w1 = vrow[1], w2 = vrow[2], w3 = vrow[3];
            acc[0]  += a * w0.x; acc[1]  += a * w0.y; acc[2]  += a * w0.z; acc[3]  += a * w0.w;
            acc[4]  += a * w1.x; acc[5]  += a * w1.y; acc[6]  += a * w1.z; acc[7]  += a * w1.w;
            acc[8]  += a * w2.x; acc[9]  += a * w2.y; acc[10] += a * w2.z; acc[11] += a * w2.w;
            acc[12] += a * w3.x; acc[13] += a * w3.y; acc[14] += a * w3.z; acc[15] += a * w3.w;
        }
        __syncthreads();
    }
    float* cdst = &g_ctx[((b * HEADS + h) * 64 + d) * 64 + eg * 16];
    #pragma unroll
    for (int c = 0; c < 16; c++) atomicAdd(&cdst[c], acc[c]);
}

// ---------------- o = qexp*rq @ ctx ; write row-major fp16 ------------------
__global__ __launch_bounds__(256) void oproj_kernel()
{
    __shared__ float cs[64][64];
    __shared__ float qt[64][65];
    __shared__ float rq[64];
    int tid = threadIdx.x;
    int h = blockIdx.y;
    int tok0 = blockIdx.x * 64;
    int b = tok0 >> 13;

    const float* csrc = &g_ctx[(b * HEADS + h) * 64 * 64];
    for (int i = tid; i < 4096; i += 256) cs[i >> 6][i & 63] = csrc[i];
    if (tid < 64) rq[tid] = 1.f / g_qsum[b * DIM + h * 64 + tid];
    __syncthreads();

    for (int i = tid; i < 64 * 64; i += 256) {
        int t = i >> 6, dd = i & 63;
        qt[t][dd] = g_q[(size_t)(tok0 + t) * 512 + h * 64 + dd] * rq[dd];
    }
    __syncthreads();

    int tx = tid & 15, ty = tid >> 4;
    float acc[4][4] = {};
    #pragma unroll
    for (int dd = 0; dd < 64; dd++) {
        float a[4], bb[4];
        #pragma unroll
        for (int i = 0; i < 4; i++) a[i] = qt[ty * 4 + i][dd];
        #pragma unroll
        for (int j = 0; j < 4; j++) bb[j] = cs[dd][tx * 4 + j];
        #pragma unroll
        for (int i = 0; i < 4; i++)
            #pragma unroll
            for (int j = 0; j < 4; j++)
                acc[i][j] += a[i] * bb[j];
    }
    #pragma unroll
    for (int i = 0; i < 4; i++) {
        int t = tok0 + ty * 4 + i;
        union { __half h2[4]; uint2 u; } ph;
        #pragma unroll
        for (int j = 0; j < 4; j++)
            ph.h2[j] = __float2half_rn(acc[i][j]);
        *(uint2*)&g_o[(size_t)t * DIM + h * 64 + tx * 4] = ph.u;
    }
}

// ---------------- launch ------------------------------------------------------
extern "C" void kernel_launch(void* const* d_in, const int* in_sizes, int n_in,
                              void* d_out, int out_size)
{
    const float* x     = (const float*)d_in[0];
    const float* ln_w  = (const float*)d_in[1];
    const float* ln_b  = (const float*)d_in[2];
    const float* w_qkv = (const float*)d_in[3];
    const float* w_out = (const float*)d_in[4];
    const float* b_out = (const float*)d_in[5];
    float* out = (float*)d_out;

    __half *p_a, *p_o, *p_wq, *p_wo;
    float* p_q;
    cudaGetSymbolAddress((void**)&p_a, g_a);
    cudaGetSymbolAddress((void**)&p_o, g_o);
    cudaGetSymbolAddress((void**)&p_wq, g_wq);
    cudaGetSymbolAddress((void**)&p_wo, g_wo);
    cudaGetSymbolAddress((void**)&p_q, g_q);

    const int LN_SMEM   = 512 * 33 * 4;
    const int GEMM_SMEM = 128 * PADT * 4;    // 68096 >= 3*STAGE = 62976
    cudaFuncSetAttribute(ln_kernel, cudaFuncAttributeMaxDynamicSharedMemorySize, LN_SMEM);
    cudaFuncSetAttribute(mma_gemm_kernel, cudaFuncAttributeMaxDynamicSharedMemorySize, GEMM_SMEM);

    init_kernel<<<(BATCH * HEADS * 64 * 64 + 255) / 256, 256>>>();
    ln_kernel<<<NTOK / 32, 256, LN_SMEM>>>(x, ln_w, ln_b);
    wconv_kernel<<<1024, 256>>>(w_qkv, w_out);
    mma_gemm_kernel<<<dim3(QKVW / 128, MTILES), 256, GEMM_SMEM>>>(
        p_a, p_wq, p_q, nullptr, QKVW, 0);
    ctx_kernel<<<dim3(NTOK / 512, HEADS), 256>>>();
    oproj_kernel<<<dim3(NTOK / 64, HEADS), 256>>>();
    mma_gemm_kernel<<<dim3(DIM / 128, MTILES), 256, GEMM_SMEM>>>(
        p_o, p_wo, out, b_out, DIM, 1);
}

// round 10
// speedup vs baseline: 1.2651x; 1.0293x over previous
#include <cuda_runtime.h>
#include <cuda_fp16.h>
#include <cstdint>

#define BATCH   4
#define SEQ     8192
#define DIM     512
#define HEADS   8
#define NTOK    32768
#define QKVW    1536
#define SCALE_Q 0.125f
#define MTILES  256
#define PADT    133

// ---------------- scratch ----------------
__device__ __align__(16) __half g_a[(size_t)NTOK * DIM];
__device__ __align__(16) __half g_o[(size_t)NTOK * DIM];
__device__ __align__(16) __half g_wq[(size_t)DIM * QKVW];
__device__ __align__(16) __half g_wo[(size_t)DIM * DIM];
__device__ __align__(16) __half g_k[(size_t)NTOK * 512];   // head-major [b][h][n][64]
__device__ __align__(16) __half g_v[(size_t)NTOK * 512];   // head-major [b][h][n][64]
__device__ float g_q[(size_t)NTOK * 512];                   // exp(q*scale), [token][512]
__device__ float g_ctx[BATCH * HEADS * 64 * 64];
__device__ float g_qsum[BATCH * DIM];

// ---------------- PTX helpers (family-target-safe only) ----------------
__device__ __forceinline__ uint32_t s2u(const void* p) {
    uint32_t a;
    asm("{ .reg .u64 t; cvta.to.shared.u64 t, %1; cvt.u32.u64 %0, t; }" : "=r"(a) : "l"(p));
    return a;
}
#define CP16(d, s)                                                            \
    asm volatile("cp.async.cg.shared.global [%0], [%1], 16;" :: "r"(d), "l"(s) : "memory")
#define CPCOMMIT() asm volatile("cp.async.commit_group;" ::: "memory")
#define CPWAIT1()  asm volatile("cp.async.wait_group 1;" ::: "memory")
#define LDSM_X4(r, a)                                                         \
    asm volatile("ldmatrix.sync.aligned.m8n8.x4.shared.b16 {%0,%1,%2,%3}, [%4];" \
        : "=r"((r)[0]), "=r"((r)[1]), "=r"((r)[2]), "=r"((r)[3]) : "r"(a))
#define LDSM_X2T(r, a)                                                        \
    asm volatile("ldmatrix.sync.aligned.m8n8.x2.trans.shared.b16 {%0,%1}, [%2];" \
        : "=r"((r)[0]), "=r"((r)[1]) : "r"(a))
#define MMA(d, a, b)                                                          \
    asm volatile("mma.sync.aligned.m16n8k16.row.col.f32.f16.f16.f32 "         \
        "{%0,%1,%2,%3},{%4,%5,%6,%7},{%8,%9},{%0,%1,%2,%3};"                  \
        : "+f"((d)[0]), "+f"((d)[1]), "+f"((d)[2]), "+f"((d)[3])              \
        : "r"((a)[0]), "r"((a)[1]), "r"((a)[2]), "r"((a)[3]),                 \
          "r"((b)[0]), "r"((b)[1]))

// ---------------- init ----------------
__global__ void init_kernel() {
    int i = blockIdx.x * 256 + threadIdx.x;
    if (i < BATCH * HEADS * 64 * 64) g_ctx[i] = 0.f;
    if (i < BATCH * DIM) g_qsum[i] = 0.f;
}

// ---------------- LayerNorm + transpose -> row-major fp16 ------------------
__global__ __launch_bounds__(256) void ln_kernel(
    const float* __restrict__ x, const float* __restrict__ lw,
    const float* __restrict__ lb)
{
    extern __shared__ float s[];               // [512][33]
    __shared__ float s_mu[32], s_rs[32];
    int tid = threadIdx.x;
    int token0 = blockIdx.x * 32;
    int b = token0 >> 13;
    int n0 = token0 & (SEQ - 1);
    const float* xb = x + (size_t)b * DIM * SEQ;

    #pragma unroll 4
    for (int i = 0; i < 64; i++) {
        int idx = i * 256 + tid;
        int d = idx >> 5, j = idx & 31;
        s[d * 33 + j] = xb[(size_t)d * SEQ + n0 + j];
    }
    __syncthreads();

    int w = tid >> 5, lane = tid & 31;
    for (int t = 0; t < 4; t++) {
        int j = w * 4 + t;
        float sum = 0.f, sq = 0.f;
        #pragma unroll
        for (int d = lane; d < DIM; d += 32) {
            float v = s[d * 33 + j];
            sum += v; sq += v * v;
        }
        #pragma unroll
        for (int o = 16; o; o >>= 1) {
            sum += __shfl_xor_sync(0xffffffffu, sum, o);
            sq  += __shfl_xor_sync(0xffffffffu, sq, o);
        }
        if (lane == 0) {
            float mu = sum * (1.f / DIM);
            float var = sq * (1.f / DIM) - mu * mu;
            s_mu[j] = mu;
            s_rs[j] = rsqrtf(var + 1e-5f);
        }
    }
    __syncthreads();

    #pragma unroll
    for (int it = 0; it < 8; it++) {
        int idx = it * 256 + tid;
        int g = idx & 63, j = idx >> 6;
        int d0 = g * 8;
        float mu = s_mu[j], rs = s_rs[j];
        union { __half h[8]; uint4 u; } ph;
        #pragma unroll
        for (int i = 0; i < 8; i++) {
            int d = d0 + i;
            float v = (s[d * 33 + j] - mu) * rs * lw[d] + lb[d];
            ph.h[i] = __float2half_rn(v);
        }
        *(uint4*)&g_a[(size_t)(token0 + j) * DIM + d0] = ph.u;
    }
}

// ---------------- weight fp32 -> fp16 ---------------------------------------
__global__ __launch_bounds__(256) void wconv_kernel(
    const float* __restrict__ wq, const float* __restrict__ wo)
{
    int stride = gridDim.x * 256;
    for (int i = blockIdx.x * 256 + threadIdx.x; i < DIM * QKVW; i += stride)
        g_wq[i] = __float2half_rn(wq[i]);
    for (int i = blockIdx.x * 256 + threadIdx.x; i < DIM * DIM; i += stride)
        g_wo[i] = __float2half_rn(wo[i]);
}

// ---------------- fp16 HMMA GEMM: C = A @ B, K=512 --------------------------
// 512 threads, 16 warps in 4x4 grid, 32x32 warp tiles (32 acc regs/thread).
// mode 0: qkv. q cols -> g_q exp fp32 + colsums; k/v cols -> g_k/g_v fp16
//         head-major [b][h][n][64].
// mode 1: out[b][dout][n] + bias (transposed store).
#define SLICE 10496              // A 6144 + B 4352
#define STAGE (2 * SLICE)        // 20992
__global__ __launch_bounds__(512, 2) void mma_gemm_kernel(
    const __half* __restrict__ A, const __half* __restrict__ B,
    float* __restrict__ C, const float* __restrict__ bias, int ldb, int mode)
{
    extern __shared__ char smem[];
    uint32_t sb = s2u(smem);
    int tid = threadIdx.x, lane = tid & 31, wid = tid >> 5;
    int m0 = blockIdx.y * 128, n0 = blockIdx.x * 128;
    int wm = (wid >> 2) * 32, wn = (wid & 3) * 32;
    bool loader = (tid < 256);

    int lt = tid & 255;
    int ar = lt >> 1, ah8 = (lt & 1) * 8;
    int bkr = lt >> 4, bn8 = (lt & 15) * 8;
    const __half* Ag = A + (size_t)(m0 + ar) * DIM + ah8;
    const __half* Bg = B + (size_t)bkr * ldb + n0 + bn8;
    uint32_t dA = sb + ar * 48 + ah8 * 2;
    uint32_t dB = sb + 6144 + bkr * 272 + bn8 * 2;

    uint32_t aAddr[2], bAddr[4];
    #pragma unroll
    for (int mi = 0; mi < 2; mi++)
        aAddr[mi] = sb + (wm + mi * 16 + (lane & 15)) * 48 + (lane >> 4) * 16;
    #pragma unroll
    for (int ni = 0; ni < 4; ni++)
        bAddr[ni] = sb + 6144 + (lane & 15) * 272 + (wn + ni * 8) * 2;

    float d[2][4][4];
    #pragma unroll
    for (int mi = 0; mi < 2; mi++)
        #pragma unroll
        for (int ni = 0; ni < 4; ni++)
            #pragma unroll
            for (int r = 0; r < 4; r++) d[mi][ni][r] = 0.f;

    if (loader) {
        #pragma unroll
        for (int p = 0; p < 2; p++) {
            #pragma unroll
            for (int s = 0; s < 2; s++) {
                uint32_t so = p * STAGE + s * SLICE;
                int ks = p * 2 + s;
                CP16(dA + so, Ag + ks * 16);
                CP16(dB + so, Bg + (size_t)ks * 16 * ldb);
            }
            CPCOMMIT();
        }
    }

    for (int kk = 0; kk < 16; kk++) {
        if (loader) CPWAIT1();
        __syncthreads();
        if (loader) {
            if (kk + 2 < 16) {
                #pragma unroll
                for (int s = 0; s < 2; s++) {
                    uint32_t so = ((kk + 2) % 3) * STAGE + s * SLICE;
                    int ks = (kk + 2) * 2 + s;
                    CP16(dA + so, Ag + ks * 16);
                    CP16(dB + so, Bg + (size_t)ks * 16 * ldb);
                }
            }
            CPCOMMIT();
        }

        #pragma unroll
        for (int s = 0; s < 2; s++) {
            uint32_t so = (kk % 3) * STAGE + s * SLICE;
            uint32_t ah[2][4], bh[4][2];
            #pragma unroll
            for (int mi = 0; mi < 2; mi++)
                LDSM_X4(ah[mi], aAddr[mi] + so);
            #pragma unroll
            for (int ni = 0; ni < 4; ni++)
                LDSM_X2T(bh[ni], bAddr[ni] + so);
            #pragma unroll
            for (int mi = 0; mi < 2; mi++)
                #pragma unroll
                for (int ni = 0; ni < 4; ni++)
                    MMA(d[mi][ni], ah[mi], bh[ni]);
        }
    }

    if (mode == 0) {
        int region = n0 >> 9;                  // 0: q, 1: k, 2: v
        if (region == 0) {
            float* qs = (float*)smem;
            __syncthreads();
            if (tid < 128) qs[tid] = 0.f;
            __syncthreads();
            #pragma unroll
            for (int mi = 0; mi < 2; mi++) {
                int r0 = m0 + wm + mi * 16 + (lane >> 2);
                #pragma unroll
                for (int ni = 0; ni < 4; ni++) {
                    int cl = wn + ni * 8 + (lane & 3) * 2;
                    float v0 = __expf(d[mi][ni][0] * SCALE_Q);
                    float v1 = __expf(d[mi][ni][1] * SCALE_Q);
                    float v2 = __expf(d[mi][ni][2] * SCALE_Q);
                    float v3 = __expf(d[mi][ni][3] * SCALE_Q);
                    atomicAdd(&qs[cl],     v0 + v2);
                    atomicAdd(&qs[cl + 1], v1 + v3);
                    *(float2*)&C[(size_t)r0 * 512 + n0 + cl]       = make_float2(v0, v1);
                    *(float2*)&C[(size_t)(r0 + 8) * 512 + n0 + cl] = make_float2(v2, v3);
                }
            }
            __syncthreads();
            if (tid < 128)
                atomicAdd(&g_qsum[(m0 >> 13) * DIM + n0 + tid], qs[tid]);
        } else {
            __half* dstbuf = (region == 1) ? g_k : g_v;
            int colbase = n0 & 511;
            #pragma unroll
            for (int mi = 0; mi < 2; mi++) {
                int r0 = m0 + wm + mi * 16 + (lane >> 2);
                int b = r0 >> 13, n = r0 & (SEQ - 1);
                #pragma unroll
                for (int ni = 0; ni < 4; ni++) {
                    int col = colbase + wn + ni * 8 + (lane & 3) * 2;
                    int h = col >> 6, dd = col & 63;
                    size_t base = ((size_t)(b * HEADS + h) * SEQ + n) * 64 + dd;
                    *(__half2*)&dstbuf[base] =
                        __floats2half2_rn(d[mi][ni][0], d[mi][ni][1]);
                    *(__half2*)&dstbuf[base + 8 * 64] =
                        __floats2half2_rn(d[mi][ni][2], d[mi][ni][3]);
                }
            }
        }
    } else {
        __syncthreads();
        float* st = (float*)smem;             // [128][PADT]
        #pragma unroll
        for (int mi = 0; mi < 2; mi++) {
            int r0 = wm + mi * 16 + (lane >> 2);
            #pragma unroll
            for (int ni = 0; ni < 4; ni++) {
                int c0 = wn + ni * 8 + (lane & 3) * 2;
                st[r0 * PADT + c0]           = d[mi][ni][0];
                st[r0 * PADT + c0 + 1]       = d[mi][ni][1];
                st[(r0 + 8) * PADT + c0]     = d[mi][ni][2];
                st[(r0 + 8) * PADT + c0 + 1] = d[mi][ni][3];
            }
        }
        __syncthreads();
        int b = m0 >> 13, nn0 = m0 & (SEQ - 1);
        float* dst = C + (size_t)b * DIM * SEQ + (size_t)n0 * SEQ + nn0;
        for (int idx = tid; idx < 16384; idx += 512) {
            int r = idx >> 7;
            int c = idx & 127;
            dst[(size_t)r * SEQ + c] = st[c * PADT + r] + bias[n0 + r];
        }
    }
}

// ---------------- k softmax + context accumulation (fp16 head-major in) -----
__global__ __launch_bounds__(256) void ctx_kernel()
{
    __shared__ float kb[16][64];
    __shared__ float vb[16][64];
    int tid = threadIdx.x;
    int h = blockIdx.y;
    int tok0 = blockIdx.x * 512;
    int b = tok0 >> 13;
    int n0 = tok0 & (SEQ - 1);
    int d = tid & 63, eg = tid >> 6;
    int ltt = tid >> 4, ld4 = (tid & 15) * 4;
    float acc[16] = {};

    size_t bh = ((size_t)(b * HEADS + h) * SEQ + n0) * 64;

    for (int t0 = 0; t0 < 512; t0 += 16) {
        size_t off = bh + (size_t)(t0 + ltt) * 64 + ld4;
        uint2 kr = *(const uint2*)&g_k[off];
        uint2 vr = *(const uint2*)&g_v[off];
        __half2 k01 = *(__half2*)&kr.x, k23 = *(__half2*)&kr.y;
        __half2 v01 = *(__half2*)&vr.x, v23 = *(__half2*)&vr.y;
        kb[ltt][ld4]     = __low2float(k01); kb[ltt][ld4 + 1] = __high2float(k01);
        kb[ltt][ld4 + 2] = __low2float(k23); kb[ltt][ld4 + 3] = __high2float(k23);
        vb[ltt][ld4]     = __low2float(v01); vb[ltt][ld4 + 1] = __high2float(v01);
        vb[ltt][ld4 + 2] = __low2float(v23); vb[ltt][ld4 + 3] = __high2float(v23);
        __syncthreads();
        {
            int w = tid >> 5, lane = tid & 31;
            #pragma unroll
            for (int u = 0; u < 2; u++) {
                int tt = w * 2 + u;
                float e0 = __expf(kb[tt][lane]);
                float e1 = __expf(kb[tt][lane + 32]);
                float su = e0 + e1;
                #pragma unroll
                for (int o = 16; o; o >>= 1) su += __shfl_xor_sync(0xffffffffu, su, o);
                float inv = 1.f / su;
                kb[tt][lane] = e0 * inv;
                kb[tt][lane + 32] = e1 * inv;
            }
        }
        __syncthreads();
        #pragma unroll
        for (int tt = 0; tt < 16; tt++) {
            float a = kb[tt][d];
            const float4* vrow = (const float4*)&vb[tt][eg * 16];
            float4 w0 = vrow[0], w1 = vrow[1], w2 = vrow[2], w3 = vrow[3];
            acc[0]  += a * w0.x; acc[1]  += a * w0.y; acc[2]  += a * w0.z; acc[3]  += a * w0.w;
            acc[4]  += a * w1.x; acc[5]  += a * w1.y; acc[6]  += a * w1.z; acc[7]  += a * w1.w;
            acc[8]  += a * w2.x; acc[9]  += a * w2.y; acc[10] += a * w2.z; acc[11] += a * w2.w;
            acc[12] += a * w3.x; acc[13] += a * w3.y; acc[14] += a * w3.z; acc[15] += a * w3.w;
        }
        __syncthreads();
    }
    float* cdst = &g_ctx[((b * HEADS + h) * 64 + d) * 64 + eg * 16];
    #pragma unroll
    for (int c = 0; c < 16; c++) atomicAdd(&cdst[c], acc[c]);
}

// ---------------- o = qexp*rq @ ctx ; write row-major fp16 ------------------
__global__ __launch_bounds__(256) void oproj_kernel()
{
    __shared__ float cs[64][64];
    __shared__ float qt[64][65];
    __shared__ float rq[64];
    int tid = threadIdx.x;
    int h = blockIdx.y;
    int tok0 = blockIdx.x * 64;
    int b = tok0 >> 13;

    const float* csrc = &g_ctx[(b * HEADS + h) * 64 * 64];
    for (int i = tid; i < 4096; i += 256) cs[i >> 6][i & 63] = csrc[i];
    if (tid < 64) rq[tid] = 1.f / g_qsum[b * DIM + h * 64 + tid];
    __syncthreads();

    for (int i = tid; i < 64 * 64; i += 256) {
        int t = i >> 6, dd = i & 63;
        qt[t][dd] = g_q[(size_t)(tok0 + t) * 512 + h * 64 + dd] * rq[dd];
    }
    __syncthreads();

    int tx = tid & 15, ty = tid >> 4;
    float acc[4][4] = {};
    #pragma unroll
    for (int dd = 0; dd < 64; dd++) {
        float a[4], bb[4];
        #pragma unroll
        for (int i = 0; i < 4; i++) a[i] = qt[ty * 4 + i][dd];
        #pragma unroll
        for (int j = 0; j < 4; j++) bb[j] = cs[dd][tx * 4 + j];
        #pragma unroll
        for (int i = 0; i < 4; i++)
            #pragma unroll
            for (int j = 0; j < 4; j++)
                acc[i][j] += a[i] * bb[j];
    }
    #pragma unroll
    for (int i = 0; i < 4; i++) {
        int t = tok0 + ty * 4 + i;
        union { __half h2[4]; uint2 u; } ph;
        #pragma unroll
        for (int j = 0; j < 4; j++)
            ph.h2[j] = __float2half_rn(acc[i][j]);
        *(uint2*)&g_o[(size_t)t * DIM + h * 64 + tx * 4] = ph.u;
    }
}

// ---------------- launch ------------------------------------------------------
extern "C" void kernel_launch(void* const* d_in, const int* in_sizes, int n_in,
                              void* d_out, int out_size)
{
    const float* x     = (const float*)d_in[0];
    const float* ln_w  = (const float*)d_in[1];
    const float* ln_b  = (const float*)d_in[2];
    const float* w_qkv = (const float*)d_in[3];
    const float* w_out = (const float*)d_in[4];
    const float* b_out = (const float*)d_in[5];
    float* out = (float*)d_out;

    __half *p_a, *p_o, *p_wq, *p_wo;
    float* p_q;
    cudaGetSymbolAddress((void**)&p_a, g_a);
    cudaGetSymbolAddress((void**)&p_o, g_o);
    cudaGetSymbolAddress((void**)&p_wq, g_wq);
    cudaGetSymbolAddress((void**)&p_wo, g_wo);
    cudaGetSymbolAddress((void**)&p_q, g_q);

    const int LN_SMEM   = 512 * 33 * 4;
    const int GEMM_SMEM = 128 * PADT * 4;    // 68096 >= 3*STAGE = 62976
    cudaFuncSetAttribute(ln_kernel, cudaFuncAttributeMaxDynamicSharedMemorySize, LN_SMEM);
    cudaFuncSetAttribute(mma_gemm_kernel, cudaFuncAttributeMaxDynamicSharedMemorySize, GEMM_SMEM);

    init_kernel<<<(BATCH * HEADS * 64 * 64 + 255) / 256, 256>>>();
    ln_kernel<<<NTOK / 32, 256, LN_SMEM>>>(x, ln_w, ln_b);
    wconv_kernel<<<1024, 256>>>(w_qkv, w_out);
    mma_gemm_kernel<<<dim3(QKVW / 128, MTILES), 512, GEMM_SMEM>>>(
        p_a, p_wq, p_q, nullptr, QKVW, 0);
    ctx_kernel<<<dim3(NTOK / 512, HEADS), 256>>>();
    oproj_kernel<<<dim3(NTOK / 64, HEADS), 256>>>();
    mma_gemm_kernel<<<dim3(DIM / 128, MTILES), 512, GEMM_SMEM>>>(
        p_o, p_wo, out, b_out, DIM, 1);
}

// round 11
// speedup vs baseline: 1.4849x; 1.1737x over previous
#include <cuda_runtime.h>
#include <cuda_fp16.h>
#include <cstdint>

#define BATCH   4
#define SEQ     8192
#define DIM     512
#define HEADS   8
#define NTOK    32768
#define QKVW    1536
#define SCALE_Q 0.125f
#define MTILES  256
#define PADT    133

// ---------------- scratch ----------------
__device__ __align__(16) __half g_a[(size_t)NTOK * DIM];
__device__ __align__(16) __half g_wq[(size_t)DIM * QKVW];
__device__ __align__(16) __half g_k[(size_t)NTOK * 512];   // head-major [b][h][n][64]
__device__ __align__(16) __half g_v[(size_t)NTOK * 512];   // head-major [b][h][n][64]
__device__ __align__(16) __half g_qh[(size_t)NTOK * 512];  // exp(q*scale) fp16
__device__ __align__(16) __half g_w2[(size_t)BATCH * DIM * DIM]; // per-batch fused ctx@w_out
__device__ float g_ctx[BATCH * HEADS * 64 * 64];
__device__ float g_qsum[BATCH * DIM];

// ---------------- PTX helpers (family-target-safe only) ----------------
__device__ __forceinline__ uint32_t s2u(const void* p) {
    uint32_t a;
    asm("{ .reg .u64 t; cvta.to.shared.u64 t, %1; cvt.u32.u64 %0, t; }" : "=r"(a) : "l"(p));
    return a;
}
#define CP16(d, s)                                                            \
    asm volatile("cp.async.cg.shared.global [%0], [%1], 16;" :: "r"(d), "l"(s) : "memory")
#define CPCOMMIT() asm volatile("cp.async.commit_group;" ::: "memory")
#define CPWAIT1()  asm volatile("cp.async.wait_group 1;" ::: "memory")
#define LDSM_X4(r, a)                                                         \
    asm volatile("ldmatrix.sync.aligned.m8n8.x4.shared.b16 {%0,%1,%2,%3}, [%4];" \
        : "=r"((r)[0]), "=r"((r)[1]), "=r"((r)[2]), "=r"((r)[3]) : "r"(a))
#define LDSM_X2T(r, a)                                                        \
    asm volatile("ldmatrix.sync.aligned.m8n8.x2.trans.shared.b16 {%0,%1}, [%2];" \
        : "=r"((r)[0]), "=r"((r)[1]) : "r"(a))
#define MMA(d, a, b)                                                          \
    asm volatile("mma.sync.aligned.m16n8k16.row.col.f32.f16.f16.f32 "         \
        "{%0,%1,%2,%3},{%4,%5,%6,%7},{%8,%9},{%0,%1,%2,%3};"                  \
        : "+f"((d)[0]), "+f"((d)[1]), "+f"((d)[2]), "+f"((d)[3])              \
        : "r"((a)[0]), "r"((a)[1]), "r"((a)[2]), "r"((a)[3]),                 \
          "r"((b)[0]), "r"((b)[1]))

// ---------------- init ----------------
__global__ void init_kernel() {
    int i = blockIdx.x * 256 + threadIdx.x;
    if (i < BATCH * HEADS * 64 * 64) g_ctx[i] = 0.f;
    if (i < BATCH * DIM) g_qsum[i] = 0.f;
}

// ---------------- LayerNorm + transpose -> row-major fp16 ------------------
__global__ __launch_bounds__(256) void ln_kernel(
    const float* __restrict__ x, const float* __restrict__ lw,
    const float* __restrict__ lb)
{
    extern __shared__ float s[];               // [512][33]
    __shared__ float s_mu[32], s_rs[32];
    int tid = threadIdx.x;
    int token0 = blockIdx.x * 32;
    int b = token0 >> 13;
    int n0 = token0 & (SEQ - 1);
    const float* xb = x + (size_t)b * DIM * SEQ;

    #pragma unroll 4
    for (int i = 0; i < 64; i++) {
        int idx = i * 256 + tid;
        int d = idx >> 5, j = idx & 31;
        s[d * 33 + j] = xb[(size_t)d * SEQ + n0 + j];
    }
    __syncthreads();

    int w = tid >> 5, lane = tid & 31;
    for (int t = 0; t < 4; t++) {
        int j = w * 4 + t;
        float sum = 0.f, sq = 0.f;
        #pragma unroll
        for (int d = lane; d < DIM; d += 32) {
            float v = s[d * 33 + j];
            sum += v; sq += v * v;
        }
        #pragma unroll
        for (int o = 16; o; o >>= 1) {
            sum += __shfl_xor_sync(0xffffffffu, sum, o);
            sq  += __shfl_xor_sync(0xffffffffu, sq, o);
        }
        if (lane == 0) {
            float mu = sum * (1.f / DIM);
            float var = sq * (1.f / DIM) - mu * mu;
            s_mu[j] = mu;
            s_rs[j] = rsqrtf(var + 1e-5f);
        }
    }
    __syncthreads();

    #pragma unroll
    for (int it = 0; it < 8; it++) {
        int idx = it * 256 + tid;
        int g = idx & 63, j = idx >> 6;
        int d0 = g * 8;
        float mu = s_mu[j], rs = s_rs[j];
        union { __half h[8]; uint4 u; } ph;
        #pragma unroll
        for (int i = 0; i < 8; i++) {
            int d = d0 + i;
            float v = (s[d * 33 + j] - mu) * rs * lw[d] + lb[d];
            ph.h[i] = __float2half_rn(v);
        }
        *(uint4*)&g_a[(size_t)(token0 + j) * DIM + d0] = ph.u;
    }
}

// ---------------- weight fp32 -> fp16 (qkv only) ----------------------------
__global__ __launch_bounds__(256) void wconv_kernel(const float* __restrict__ wq)
{
    int stride = gridDim.x * 256;
    for (int i = blockIdx.x * 256 + threadIdx.x; i < DIM * QKVW; i += stride)
        g_wq[i] = __float2half_rn(wq[i]);
}

// ---------------- fp16 HMMA GEMM: C = A @ B, K=512 --------------------------
// 512 threads, 16 warps in 4x4 grid, 32x32 warp tiles.
// mode 0: qkv. q cols -> g_qh fp16 exp + colsums; k/v -> g_k/g_v fp16 head-major.
// mode 1: out[b][dout][n] = qh @ W2_b + bias (B indexed per batch).
#define SLICE 10496              // A 6144 + B 4352
#define STAGE (2 * SLICE)        // 20992
__global__ __launch_bounds__(512, 2) void mma_gemm_kernel(
    const __half* __restrict__ A, const __half* __restrict__ B,
    float* __restrict__ C, const float* __restrict__ bias, int ldb, int mode)
{
    extern __shared__ char smem[];
    uint32_t sb = s2u(smem);
    int tid = threadIdx.x, lane = tid & 31, wid = tid >> 5;
    int m0 = blockIdx.y * 128, n0 = blockIdx.x * 128;
    int wm = (wid >> 2) * 32, wn = (wid & 3) * 32;
    bool loader = (tid < 256);

    if (mode == 1) B += (size_t)(m0 >> 13) * DIM * DIM;   // per-batch W2

    int lt = tid & 255;
    int ar = lt >> 1, ah8 = (lt & 1) * 8;
    int bkr = lt >> 4, bn8 = (lt & 15) * 8;
    const __half* Ag = A + (size_t)(m0 + ar) * DIM + ah8;
    const __half* Bg = B + (size_t)bkr * ldb + n0 + bn8;
    uint32_t dA = sb + ar * 48 + ah8 * 2;
    uint32_t dB = sb + 6144 + bkr * 272 + bn8 * 2;

    uint32_t aAddr[2], bAddr[4];
    #pragma unroll
    for (int mi = 0; mi < 2; mi++)
        aAddr[mi] = sb + (wm + mi * 16 + (lane & 15)) * 48 + (lane >> 4) * 16;
    #pragma unroll
    for (int ni = 0; ni < 4; ni++)
        bAddr[ni] = sb + 6144 + (lane & 15) * 272 + (wn + ni * 8) * 2;

    float d[2][4][4];
    #pragma unroll
    for (int mi = 0; mi < 2; mi++)
        #pragma unroll
        for (int ni = 0; ni < 4; ni++)
            #pragma unroll
            for (int r = 0; r < 4; r++) d[mi][ni][r] = 0.f;

    if (loader) {
        #pragma unroll
        for (int p = 0; p < 2; p++) {
            #pragma unroll
            for (int s = 0; s < 2; s++) {
                uint32_t so = p * STAGE + s * SLICE;
                int ks = p * 2 + s;
                CP16(dA + so, Ag + ks * 16);
                CP16(dB + so, Bg + (size_t)ks * 16 * ldb);
            }
            CPCOMMIT();
        }
    }

    for (int kk = 0; kk < 16; kk++) {
        if (loader) CPWAIT1();
        __syncthreads();
        if (loader) {
            if (kk + 2 < 16) {
                #pragma unroll
                for (int s = 0; s < 2; s++) {
                    uint32_t so = ((kk + 2) % 3) * STAGE + s * SLICE;
                    int ks = (kk + 2) * 2 + s;
                    CP16(dA + so, Ag + ks * 16);
                    CP16(dB + so, Bg + (size_t)ks * 16 * ldb);
                }
            }
            CPCOMMIT();
        }

        #pragma unroll
        for (int s = 0; s < 2; s++) {
            uint32_t so = (kk % 3) * STAGE + s * SLICE;
            uint32_t ah[2][4], bh[4][2];
            #pragma unroll
            for (int mi = 0; mi < 2; mi++)
                LDSM_X4(ah[mi], aAddr[mi] + so);
            #pragma unroll
            for (int ni = 0; ni < 4; ni++)
                LDSM_X2T(bh[ni], bAddr[ni] + so);
            #pragma unroll
            for (int mi = 0; mi < 2; mi++)
                #pragma unroll
                for (int ni = 0; ni < 4; ni++)
                    MMA(d[mi][ni], ah[mi], bh[ni]);
        }
    }

    if (mode == 0) {
        int region = n0 >> 9;                  // 0: q, 1: k, 2: v
        if (region == 0) {
            float* qs = (float*)smem;
            __syncthreads();
            if (tid < 128) qs[tid] = 0.f;
            __syncthreads();
            #pragma unroll
            for (int mi = 0; mi < 2; mi++) {
                int r0 = m0 + wm + mi * 16 + (lane >> 2);
                #pragma unroll
                for (int ni = 0; ni < 4; ni++) {
                    int cl = wn + ni * 8 + (lane & 3) * 2;
                    float v0 = __expf(d[mi][ni][0] * SCALE_Q);
                    float v1 = __expf(d[mi][ni][1] * SCALE_Q);
                    float v2 = __expf(d[mi][ni][2] * SCALE_Q);
                    float v3 = __expf(d[mi][ni][3] * SCALE_Q);
                    atomicAdd(&qs[cl],     v0 + v2);
                    atomicAdd(&qs[cl + 1], v1 + v3);
                    *(__half2*)&g_qh[(size_t)r0 * 512 + n0 + cl] =
                        __floats2half2_rn(v0, v1);
                    *(__half2*)&g_qh[(size_t)(r0 + 8) * 512 + n0 + cl] =
                        __floats2half2_rn(v2, v3);
                }
            }
            __syncthreads();
            if (tid < 128)
                atomicAdd(&g_qsum[(m0 >> 13) * DIM + n0 + tid], qs[tid]);
        } else {
            __half* dstbuf = (region == 1) ? g_k : g_v;
            int colbase = n0 & 511;
            #pragma unroll
            for (int mi = 0; mi < 2; mi++) {
                int r0 = m0 + wm + mi * 16 + (lane >> 2);
                int b = r0 >> 13, n = r0 & (SEQ - 1);
                #pragma unroll
                for (int ni = 0; ni < 4; ni++) {
                    int col = colbase + wn + ni * 8 + (lane & 3) * 2;
                    int h = col >> 6, dd = col & 63;
                    size_t base = ((size_t)(b * HEADS + h) * SEQ + n) * 64 + dd;
                    *(__half2*)&dstbuf[base] =
                        __floats2half2_rn(d[mi][ni][0], d[mi][ni][1]);
                    *(__half2*)&dstbuf[base + 8 * 64] =
                        __floats2half2_rn(d[mi][ni][2], d[mi][ni][3]);
                }
            }
        }
    } else {
        __syncthreads();
        float* st = (float*)smem;             // [128][PADT]
        #pragma unroll
        for (int mi = 0; mi < 2; mi++) {
            int r0 = wm + mi * 16 + (lane >> 2);
            #pragma unroll
            for (int ni = 0; ni < 4; ni++) {
                int c0 = wn + ni * 8 + (lane & 3) * 2;
                st[r0 * PADT + c0]           = d[mi][ni][0];
                st[r0 * PADT + c0 + 1]       = d[mi][ni][1];
                st[(r0 + 8) * PADT + c0]     = d[mi][ni][2];
                st[(r0 + 8) * PADT + c0 + 1] = d[mi][ni][3];
            }
        }
        __syncthreads();
        int b = m0 >> 13, nn0 = m0 & (SEQ - 1);
        float* dst = C + (size_t)b * DIM * SEQ + (size_t)n0 * SEQ + nn0;
        for (int idx = tid; idx < 16384; idx += 512) {
            int r = idx >> 7;
            int c = idx & 127;
            dst[(size_t)r * SEQ + c] = st[c * PADT + r] + bias[n0 + r];
        }
    }
}

// ---------------- k softmax + context accumulation (fp16 head-major in) -----
__global__ __launch_bounds__(256) void ctx_kernel()
{
    __shared__ float kb[16][64];
    __shared__ float vb[16][64];
    int tid = threadIdx.x;
    int h = blockIdx.y;
    int tok0 = blockIdx.x * 512;
    int b = tok0 >> 13;
    int n0 = tok0 & (SEQ - 1);
    int d = tid & 63, eg = tid >> 6;
    int ltt = tid >> 4, ld4 = (tid & 15) * 4;
    float acc[16] = {};

    size_t bh = ((size_t)(b * HEADS + h) * SEQ + n0) * 64;

    for (int t0 = 0; t0 < 512; t0 += 16) {
        size_t off = bh + (size_t)(t0 + ltt) * 64 + ld4;
        uint2 kr = *(const uint2*)&g_k[off];
        uint2 vr = *(const uint2*)&g_v[off];
        __half2 k01 = *(__half2*)&kr.x, k23 = *(__half2*)&kr.y;
        __half2 v01 = *(__half2*)&vr.x, v23 = *(__half2*)&vr.y;
        kb[ltt][ld4]     = __low2float(k01); kb[ltt][ld4 + 1] = __high2float(k01);
        kb[ltt][ld4 + 2] = __low2float(k23); kb[ltt][ld4 + 3] = __high2float(k23);
        vb[ltt][ld4]     = __low2float(v01); vb[ltt][ld4 + 1] = __high2float(v01);
        vb[ltt][ld4 + 2] = __low2float(v23); vb[ltt][ld4 + 3] = __high2float(v23);
        __syncthreads();
        {
            int w = tid >> 5, lane = tid & 31;
            #pragma unroll
            for (int u = 0; u < 2; u++) {
                int tt = w * 2 + u;
                float e0 = __expf(kb[tt][lane]);
                float e1 = __expf(kb[tt][lane + 32]);
                float su = e0 + e1;
                #pragma unroll
                for (int o = 16; o; o >>= 1) su += __shfl_xor_sync(0xffffffffu, su, o);
                float inv = 1.f / su;
                kb[tt][lane] = e0 * inv;
                kb[tt][lane + 32] = e1 * inv;
            }
        }
        __syncthreads();
        #pragma unroll
        for (int tt = 0; tt < 16; tt++) {
            float a = kb[tt][d];
            const float4* vrow = (const float4*)&vb[tt][eg * 16];
            float4 w0 = vrow[0], w1 = vrow[1], w2 = vrow[2], w3 = vrow[3];
            acc[0]  += a * w0.x; acc[1]  += a * w0.y; acc[2]  += a * w0.z; acc[3]  += a * w0.w;
            acc[4]  += a * w1.x; acc[5]  += a * w1.y; acc[6]  += a * w1.z; acc[7]  += a * w1.w;
            acc[8]  += a * w2.x; acc[9]  += a * w2.y; acc[10] += a * w2.z; acc[11] += a * w2.w;
            acc[12] += a * w3.x; acc[13] += a * w3.y; acc[14] += a * w3.z; acc[15] += a * w3.w;
        }
        __syncthreads();
    }
    float* cdst = &g_ctx[((b * HEADS + h) * 64 + d) * 64 + eg * 16];
    #pragma unroll
    for (int c = 0; c < 16; c++) atomicAdd(&cdst[c], acc[c]);
}

// ---------------- W2_b = vstack_h( diag(rq_h) * (ctx_bh @ w_out_h) ) --------
// grid (4 col-chunks, 32 bh), 256 threads
__global__ __launch_bounds__(256) void w2_kernel(const float* __restrict__ w_out)
{
    __shared__ float cs[64][65];
    __shared__ float ws[64][128];
    int tid = threadIdx.x;
    int jc = blockIdx.x;                   // 128-wide output column chunk
    int bh = blockIdx.y;
    int b = bh >> 3, h = bh & 7;

    const float* csrc = g_ctx + (size_t)bh * 4096;
    for (int i = tid; i < 4096; i += 256) cs[i >> 6][i & 63] = csrc[i];
    for (int i = tid; i < 64 * 128; i += 256) {
        int e = i >> 7, j = i & 127;
        ws[e][j] = w_out[(size_t)(h * 64 + e) * DIM + jc * 128 + j];
    }
    __syncthreads();

    int dd = tid >> 2, j0 = (tid & 3) * 32;
    float rq = 1.f / g_qsum[b * DIM + h * 64 + dd];
    float acc[32] = {};
    #pragma unroll 8
    for (int e = 0; e < 64; e++) {
        float a = cs[dd][e];
        #pragma unroll
        for (int j = 0; j < 32; j++) acc[j] += a * ws[e][j0 + j];
    }
    __half* dst = g_w2 + ((size_t)b * DIM + h * 64 + dd) * DIM + jc * 128 + j0;
    #pragma unroll
    for (int j = 0; j < 32; j += 2)
        *(__half2*)&dst[j] = __floats2half2_rn(acc[j] * rq, acc[j + 1] * rq);
}

// ---------------- launch ------------------------------------------------------
extern "C" void kernel_launch(void* const* d_in, const int* in_sizes, int n_in,
                              void* d_out, int out_size)
{
    const float* x     = (const float*)d_in[0];
    const float* ln_w  = (const float*)d_in[1];
    const float* ln_b  = (const float*)d_in[2];
    const float* w_qkv = (const float*)d_in[3];
    const float* w_out = (const float*)d_in[4];
    const float* b_out = (const float*)d_in[5];
    float* out = (float*)d_out;

    __half *p_a, *p_wq, *p_qh, *p_w2;
    cudaGetSymbolAddress((void**)&p_a, g_a);
    cudaGetSymbolAddress((void**)&p_wq, g_wq);
    cudaGetSymbolAddress((void**)&p_qh, g_qh);
    cudaGetSymbolAddress((void**)&p_w2, g_w2);

    const int LN_SMEM   = 512 * 33 * 4;
    const int GEMM_SMEM = 128 * PADT * 4;    // 68096 >= 3*STAGE = 62976
    cudaFuncSetAttribute(ln_kernel, cudaFuncAttributeMaxDynamicSharedMemorySize, LN_SMEM);
    cudaFuncSetAttribute(mma_gemm_kernel, cudaFuncAttributeMaxDynamicSharedMemorySize, GEMM_SMEM);

    init_kernel<<<(BATCH * HEADS * 64 * 64 + 255) / 256, 256>>>();
    ln_kernel<<<NTOK / 32, 256, LN_SMEM>>>(x, ln_w, ln_b);
    wconv_kernel<<<768, 256>>>(w_qkv);
    mma_gemm_kernel<<<dim3(QKVW / 128, MTILES), 512, GEMM_SMEM>>>(
        p_a, p_wq, nullptr, nullptr, QKVW, 0);
    ctx_kernel<<<dim3(NTOK / 512, HEADS), 256>>>();
    w2_kernel<<<dim3(4, 32), 256>>>(w_out);
    mma_gemm_kernel<<<dim3(DIM / 128, MTILES), 512, GEMM_SMEM>>>(
        p_qh, p_w2, out, b_out, DIM, 1);
}

// round 12
// speedup vs baseline: 1.7622x; 1.1867x over previous
#include <cuda_runtime.h>
#include <cuda_fp16.h>
#include <cstdint>

#define BATCH   4
#define SEQ     8192
#define DIM     512
#define HEADS   8
#define NTOK    32768
#define QKVW    1536
#define SCALE_Q 0.125f
#define MTILES  256
#define PADT    133

// ---------------- scratch ----------------
__device__ __align__(16) __half g_a[(size_t)NTOK * DIM];
__device__ __align__(16) __half g_wq[(size_t)DIM * QKVW];
__device__ __align__(16) __half g_k[(size_t)NTOK * 512];   // head-major [b][h][n][64]
__device__ __align__(16) __half g_v[(size_t)NTOK * 512];   // head-major [b][h][n][64]
__device__ __align__(16) __half g_qh[(size_t)NTOK * 512];  // exp(q*scale) fp16
__device__ __align__(16) __half g_w2[(size_t)BATCH * DIM * DIM]; // per-batch fused ctx@w_out
__device__ float g_ctx[BATCH * HEADS * 64 * 64];
__device__ float g_qsum[BATCH * DIM];

// ---------------- PTX helpers (family-target-safe only) ----------------
__device__ __forceinline__ uint32_t s2u(const void* p) {
    uint32_t a;
    asm("{ .reg .u64 t; cvta.to.shared.u64 t, %1; cvt.u32.u64 %0, t; }" : "=r"(a) : "l"(p));
    return a;
}
#define CP16(d, s)                                                            \
    asm volatile("cp.async.cg.shared.global [%0], [%1], 16;" :: "r"(d), "l"(s) : "memory")
#define CPCOMMIT() asm volatile("cp.async.commit_group;" ::: "memory")
#define CPWAIT1()  asm volatile("cp.async.wait_group 1;" ::: "memory")
#define LDSM_X4(r, a)                                                         \
    asm volatile("ldmatrix.sync.aligned.m8n8.x4.shared.b16 {%0,%1,%2,%3}, [%4];" \
        : "=r"((r)[0]), "=r"((r)[1]), "=r"((r)[2]), "=r"((r)[3]) : "r"(a))
#define LDSM_X4T(r, a)                                                        \
    asm volatile("ldmatrix.sync.aligned.m8n8.x4.trans.shared.b16 {%0,%1,%2,%3}, [%4];" \
        : "=r"((r)[0]), "=r"((r)[1]), "=r"((r)[2]), "=r"((r)[3]) : "r"(a))
#define LDSM_X2T(r, a)                                                        \
    asm volatile("ldmatrix.sync.aligned.m8n8.x2.trans.shared.b16 {%0,%1}, [%2];" \
        : "=r"((r)[0]), "=r"((r)[1]) : "r"(a))
#define MMA(d, a, b)                                                          \
    asm volatile("mma.sync.aligned.m16n8k16.row.col.f32.f16.f16.f32 "         \
        "{%0,%1,%2,%3},{%4,%5,%6,%7},{%8,%9},{%0,%1,%2,%3};"                  \
        : "+f"((d)[0]), "+f"((d)[1]), "+f"((d)[2]), "+f"((d)[3])              \
        : "r"((a)[0]), "r"((a)[1]), "r"((a)[2]), "r"((a)[3]),                 \
          "r"((b)[0]), "r"((b)[1]))

// ---------------- init ----------------
__global__ void init_kernel() {
    int i = blockIdx.x * 256 + threadIdx.x;
    if (i < BATCH * HEADS * 64 * 64) g_ctx[i] = 0.f;
    if (i < BATCH * DIM) g_qsum[i] = 0.f;
}

// ---------------- LayerNorm + transpose -> row-major fp16 ------------------
__global__ __launch_bounds__(256) void ln_kernel(
    const float* __restrict__ x, const float* __restrict__ lw,
    const float* __restrict__ lb)
{
    extern __shared__ float s[];               // [512][33]
    __shared__ float s_mu[32], s_rs[32];
    int tid = threadIdx.x;
    int token0 = blockIdx.x * 32;
    int b = token0 >> 13;
    int n0 = token0 & (SEQ - 1);
    const float* xb = x + (size_t)b * DIM * SEQ;

    #pragma unroll 4
    for (int i = 0; i < 64; i++) {
        int idx = i * 256 + tid;
        int d = idx >> 5, j = idx & 31;
        s[d * 33 + j] = xb[(size_t)d * SEQ + n0 + j];
    }
    __syncthreads();

    int w = tid >> 5, lane = tid & 31;
    for (int t = 0; t < 4; t++) {
        int j = w * 4 + t;
        float sum = 0.f, sq = 0.f;
        #pragma unroll
        for (int d = lane; d < DIM; d += 32) {
            float v = s[d * 33 + j];
            sum += v; sq += v * v;
        }
        #pragma unroll
        for (int o = 16; o; o >>= 1) {
            sum += __shfl_xor_sync(0xffffffffu, sum, o);
            sq  += __shfl_xor_sync(0xffffffffu, sq, o);
        }
        if (lane == 0) {
            float mu = sum * (1.f / DIM);
            float var = sq * (1.f / DIM) - mu * mu;
            s_mu[j] = mu;
            s_rs[j] = rsqrtf(var + 1e-5f);
        }
    }
    __syncthreads();

    #pragma unroll
    for (int it = 0; it < 8; it++) {
        int idx = it * 256 + tid;
        int g = idx & 63, j = idx >> 6;
        int d0 = g * 8;
        float mu = s_mu[j], rs = s_rs[j];
        union { __half h[8]; uint4 u; } ph;
        #pragma unroll
        for (int i = 0; i < 8; i++) {
            int d = d0 + i;
            float v = (s[d * 33 + j] - mu) * rs * lw[d] + lb[d];
            ph.h[i] = __float2half_rn(v);
        }
        *(uint4*)&g_a[(size_t)(token0 + j) * DIM + d0] = ph.u;
    }
}

// ---------------- weight fp32 -> fp16 (qkv only) ----------------------------
__global__ __launch_bounds__(256) void wconv_kernel(const float* __restrict__ wq)
{
    int stride = gridDim.x * 256;
    for (int i = blockIdx.x * 256 + threadIdx.x; i < DIM * QKVW; i += stride)
        g_wq[i] = __float2half_rn(wq[i]);
}

// ---------------- fp16 HMMA GEMM: C = A @ B, K=512 --------------------------
// 512 threads, 16 warps in 4x4 grid, 32x32 warp tiles.
// mode 0: qkv. q cols -> g_qh fp16 exp + colsums; k/v -> g_k/g_v fp16 head-major.
// mode 1: out[b][dout][n] = qh @ W2_b + bias (B indexed per batch).
#define SLICE 10496              // A 6144 + B 4352
#define STAGE (2 * SLICE)        // 20992
__global__ __launch_bounds__(512, 2) void mma_gemm_kernel(
    const __half* __restrict__ A, const __half* __restrict__ B,
    float* __restrict__ C, const float* __restrict__ bias, int ldb, int mode)
{
    extern __shared__ char smem[];
    uint32_t sb = s2u(smem);
    int tid = threadIdx.x, lane = tid & 31, wid = tid >> 5;
    int m0 = blockIdx.y * 128, n0 = blockIdx.x * 128;
    int wm = (wid >> 2) * 32, wn = (wid & 3) * 32;
    bool loader = (tid < 256);

    if (mode == 1) B += (size_t)(m0 >> 13) * DIM * DIM;   // per-batch W2

    int lt = tid & 255;
    int ar = lt >> 1, ah8 = (lt & 1) * 8;
    int bkr = lt >> 4, bn8 = (lt & 15) * 8;
    const __half* Ag = A + (size_t)(m0 + ar) * DIM + ah8;
    const __half* Bg = B + (size_t)bkr * ldb + n0 + bn8;
    uint32_t dA = sb + ar * 48 + ah8 * 2;
    uint32_t dB = sb + 6144 + bkr * 272 + bn8 * 2;

    uint32_t aAddr[2], bAddr[4];
    #pragma unroll
    for (int mi = 0; mi < 2; mi++)
        aAddr[mi] = sb + (wm + mi * 16 + (lane & 15)) * 48 + (lane >> 4) * 16;
    #pragma unroll
    for (int ni = 0; ni < 4; ni++)
        bAddr[ni] = sb + 6144 + (lane & 15) * 272 + (wn + ni * 8) * 2;

    float d[2][4][4];
    #pragma unroll
    for (int mi = 0; mi < 2; mi++)
        #pragma unroll
        for (int ni = 0; ni < 4; ni++)
            #pragma unroll
            for (int r = 0; r < 4; r++) d[mi][ni][r] = 0.f;

    if (loader) {
        #pragma unroll
        for (int p = 0; p < 2; p++) {
            #pragma unroll
            for (int s = 0; s < 2; s++) {
                uint32_t so = p * STAGE + s * SLICE;
                int ks = p * 2 + s;
                CP16(dA + so, Ag + ks * 16);
                CP16(dB + so, Bg + (size_t)ks * 16 * ldb);
            }
            CPCOMMIT();
        }
    }

    for (int kk = 0; kk < 16; kk++) {
        if (loader) CPWAIT1();
        __syncthreads();
        if (loader) {
            if (kk + 2 < 16) {
                #pragma unroll
                for (int s = 0; s < 2; s++) {
                    uint32_t so = ((kk + 2) % 3) * STAGE + s * SLICE;
                    int ks = (kk + 2) * 2 + s;
                    CP16(dA + so, Ag + ks * 16);
                    CP16(dB + so, Bg + (size_t)ks * 16 * ldb);
                }
            }
            CPCOMMIT();
        }

        #pragma unroll
        for (int s = 0; s < 2; s++) {
            uint32_t so = (kk % 3) * STAGE + s * SLICE;
            uint32_t ah[2][4], bh[4][2];
            #pragma unroll
            for (int mi = 0; mi < 2; mi++)
                LDSM_X4(ah[mi], aAddr[mi] + so);
            #pragma unroll
            for (int ni = 0; ni < 4; ni++)
                LDSM_X2T(bh[ni], bAddr[ni] + so);
            #pragma unroll
            for (int mi = 0; mi < 2; mi++)
                #pragma unroll
                for (int ni = 0; ni < 4; ni++)
                    MMA(d[mi][ni], ah[mi], bh[ni]);
        }
    }

    if (mode == 0) {
        int region = n0 >> 9;                  // 0: q, 1: k, 2: v
        if (region == 0) {
            float* qs = (float*)smem;
            __syncthreads();
            if (tid < 128) qs[tid] = 0.f;
            __syncthreads();
            #pragma unroll
            for (int mi = 0; mi < 2; mi++) {
                int r0 = m0 + wm + mi * 16 + (lane >> 2);
                #pragma unroll
                for (int ni = 0; ni < 4; ni++) {
                    int cl = wn + ni * 8 + (lane & 3) * 2;
                    float v0 = __expf(d[mi][ni][0] * SCALE_Q);
                    float v1 = __expf(d[mi][ni][1] * SCALE_Q);
                    float v2 = __expf(d[mi][ni][2] * SCALE_Q);
                    float v3 = __expf(d[mi][ni][3] * SCALE_Q);
                    atomicAdd(&qs[cl],     v0 + v2);
                    atomicAdd(&qs[cl + 1], v1 + v3);
                    *(__half2*)&g_qh[(size_t)r0 * 512 + n0 + cl] =
                        __floats2half2_rn(v0, v1);
                    *(__half2*)&g_qh[(size_t)(r0 + 8) * 512 + n0 + cl] =
                        __floats2half2_rn(v2, v3);
                }
            }
            __syncthreads();
            if (tid < 128)
                atomicAdd(&g_qsum[(m0 >> 13) * DIM + n0 + tid], qs[tid]);
        } else {
            __half* dstbuf = (region == 1) ? g_k : g_v;
            int colbase = n0 & 511;
            #pragma unroll
            for (int mi = 0; mi < 2; mi++) {
                int r0 = m0 + wm + mi * 16 + (lane >> 2);
                int b = r0 >> 13, n = r0 & (SEQ - 1);
                #pragma unroll
                for (int ni = 0; ni < 4; ni++) {
                    int col = colbase + wn + ni * 8 + (lane & 3) * 2;
                    int h = col >> 6, dd = col & 63;
                    size_t base = ((size_t)(b * HEADS + h) * SEQ + n) * 64 + dd;
                    *(__half2*)&dstbuf[base] =
                        __floats2half2_rn(d[mi][ni][0], d[mi][ni][1]);
                    *(__half2*)&dstbuf[base + 8 * 64] =
                        __floats2half2_rn(d[mi][ni][2], d[mi][ni][3]);
                }
            }
        }
    } else {
        __syncthreads();
        float* st = (float*)smem;             // [128][PADT]
        #pragma unroll
        for (int mi = 0; mi < 2; mi++) {
            int r0 = wm + mi * 16 + (lane >> 2);
            #pragma unroll
            for (int ni = 0; ni < 4; ni++) {
                int c0 = wn + ni * 8 + (lane & 3) * 2;
                st[r0 * PADT + c0]           = d[mi][ni][0];
                st[r0 * PADT + c0 + 1]       = d[mi][ni][1];
                st[(r0 + 8) * PADT + c0]     = d[mi][ni][2];
                st[(r0 + 8) * PADT + c0 + 1] = d[mi][ni][3];
            }
        }
        __syncthreads();
        int b = m0 >> 13, nn0 = m0 & (SEQ - 1);
        float* dst = C + (size_t)b * DIM * SEQ + (size_t)n0 * SEQ + nn0;
        for (int idx = tid; idx < 16384; idx += 512) {
            int r = idx >> 7;
            int c = idx & 127;
            dst[(size_t)r * SEQ + c] = st[c * PADT + r] + bias[n0 + r];
        }
    }
}

// ---------------- ctx = softmax_d(k)^T @ v per (b,h) on tensor cores --------
// grid (SEQ/1024, 32 bh), 256 threads, 8 warps: 16x32 warp tiles over 64x64.
#define TOKCH 1024
#define SUBT  128
#define KTP   72                 // padded row stride in halfs (144B)
__global__ __launch_bounds__(256) void ctx_mma_kernel()
{
    __shared__ __half kt[SUBT * KTP];
    __shared__ __half vt[SUBT * KTP];
    int tid = threadIdx.x, lane = tid & 31, wid = tid >> 5;
    int bh = blockIdx.y;
    int tok0 = blockIdx.x * TOKCH;
    const __half* kbase = g_k + (size_t)bh * SEQ * 64;
    const __half* vbase = g_v + (size_t)bh * SEQ * 64;

    int wm = (wid & 3) * 16, wn = (wid >> 2) * 32;
    // A (k-hat^T) trans-ldmatrix lane address: matrices (m0,k0),(m8,k0),(m0,k8),(m8,k8)
    int l7 = lane & 7, sel = lane >> 3;
    uint32_t aBase = s2u(kt) + (uint32_t)((((sel >> 1) * 8) + l7) * KTP + wm + (sel & 1) * 8) * 2;
    uint32_t bBase = s2u(vt) + (uint32_t)((lane & 15) * KTP + wn) * 2;

    float acc[4][4] = {};
    int t = tid >> 1, h4 = tid & 1;

    for (int st0 = 0; st0 < TOKCH; st0 += SUBT) {
        // load k (32 halfs per thread), softmax over d=64 via pair shuffle
        const uint4* kr4 = (const uint4*)(kbase + (size_t)(tok0 + st0 + t) * 64 + h4 * 32);
        uint4 kr[4];
        #pragma unroll
        for (int i = 0; i < 4; i++) kr[i] = kr4[i];
        float e[32];
        float s = 0.f;
        #pragma unroll
        for (int i = 0; i < 4; i++) {
            const __half2* hp = (const __half2*)&kr[i];
            #pragma unroll
            for (int j = 0; j < 4; j++) {
                float2 f = __half22float2(hp[j]);
                float e0 = __expf(f.x), e1 = __expf(f.y);
                e[i * 8 + j * 2] = e0;
                e[i * 8 + j * 2 + 1] = e1;
                s += e0 + e1;
            }
        }
        s += __shfl_xor_sync(0xffffffffu, s, 1);
        float inv = 1.f / s;
        #pragma unroll
        for (int i = 0; i < 4; i++) {
            uint4 kw;
            __half2* op = (__half2*)&kw;
            #pragma unroll
            for (int j = 0; j < 4; j++)
                op[j] = __floats2half2_rn(e[i * 8 + j * 2] * inv,
                                          e[i * 8 + j * 2 + 1] * inv);
            *(uint4*)&kt[t * KTP + h4 * 32 + i * 8] = kw;
        }
        // copy v
        const uint4* vr4 = (const uint4*)(vbase + (size_t)(tok0 + st0 + t) * 64 + h4 * 32);
        #pragma unroll
        for (int i = 0; i < 4; i++)
            *(uint4*)&vt[t * KTP + h4 * 32 + i * 8] = vr4[i];
        __syncthreads();

        #pragma unroll
        for (int k16 = 0; k16 < SUBT; k16 += 16) {
            uint32_t a[4];
            LDSM_X4T(a, aBase + (uint32_t)k16 * (KTP * 2));
            #pragma unroll
            for (int ni = 0; ni < 4; ni++) {
                uint32_t bb[2];
                LDSM_X2T(bb, bBase + (uint32_t)k16 * (KTP * 2) + ni * 16);
                MMA(acc[ni], a, bb);
            }
        }
        __syncthreads();
    }

    float* cb = g_ctx + (size_t)bh * 4096;
    int r = wm + (lane >> 2);
    #pragma unroll
    for (int ni = 0; ni < 4; ni++) {
        int c = wn + ni * 8 + (lane & 3) * 2;
        atomicAdd(&cb[r * 64 + c],           acc[ni][0]);
        atomicAdd(&cb[r * 64 + c + 1],       acc[ni][1]);
        atomicAdd(&cb[(r + 8) * 64 + c],     acc[ni][2]);
        atomicAdd(&cb[(r + 8) * 64 + c + 1], acc[ni][3]);
    }
}

// ---------------- W2_b = vstack_h( diag(rq_h) * (ctx_bh @ w_out_h) ) --------
__global__ __launch_bounds__(256) void w2_kernel(const float* __restrict__ w_out)
{
    __shared__ float cs[64][65];
    __shared__ float ws[64][128];
    int tid = threadIdx.x;
    int jc = blockIdx.x;                   // 128-wide output column chunk
    int bh = blockIdx.y;
    int b = bh >> 3, h = bh & 7;

    const float* csrc = g_ctx + (size_t)bh * 4096;
    for (int i = tid; i < 4096; i += 256) cs[i >> 6][i & 63] = csrc[i];
    for (int i = tid; i < 64 * 128; i += 256) {
        int e = i >> 7, j = i & 127;
        ws[e][j] = w_out[(size_t)(h * 64 + e) * DIM + jc * 128 + j];
    }
    __syncthreads();

    int dd = tid >> 2, j0 = (tid & 3) * 32;
    float rq = 1.f / g_qsum[b * DIM + h * 64 + dd];
    float acc[32] = {};
    #pragma unroll 8
    for (int e = 0; e < 64; e++) {
        float a = cs[dd][e];
        #pragma unroll
        for (int j = 0; j < 32; j++) acc[j] += a * ws[e][j0 + j];
    }
    __half* dst = g_w2 + ((size_t)b * DIM + h * 64 + dd) * DIM + jc * 128 + j0;
    #pragma unroll
    for (int j = 0; j < 32; j += 2)
        *(__half2*)&dst[j] = __floats2half2_rn(acc[j] * rq, acc[j + 1] * rq);
}

// ---------------- launch ------------------------------------------------------
extern "C" void kernel_launch(void* const* d_in, const int* in_sizes, int n_in,
                              void* d_out, int out_size)
{
    const float* x     = (const float*)d_in[0];
    const float* ln_w  = (const float*)d_in[1];
    const float* ln_b  = (const float*)d_in[2];
    const float* w_qkv = (const float*)d_in[3];
    const float* w_out = (const float*)d_in[4];
    const float* b_out = (const float*)d_in[5];
    float* out = (float*)d_out;

    __half *p_a, *p_wq, *p_qh, *p_w2;
    cudaGetSymbolAddress((void**)&p_a, g_a);
    cudaGetSymbolAddress((void**)&p_wq, g_wq);
    cudaGetSymbolAddress((void**)&p_qh, g_qh);
    cudaGetSymbolAddress((void**)&p_w2, g_w2);

    const int LN_SMEM   = 512 * 33 * 4;
    const int GEMM_SMEM = 128 * PADT * 4;    // 68096 >= 3*STAGE = 62976
    cudaFuncSetAttribute(ln_kernel, cudaFuncAttributeMaxDynamicSharedMemorySize, LN_SMEM);
    cudaFuncSetAttribute(mma_gemm_kernel, cudaFuncAttributeMaxDynamicSharedMemorySize, GEMM_SMEM);

    init_kernel<<<(BATCH * HEADS * 64 * 64 + 255) / 256, 256>>>();
    ln_kernel<<<NTOK / 32, 256, LN_SMEM>>>(x, ln_w, ln_b);
    wconv_kernel<<<768, 256>>>(w_qkv);
    mma_gemm_kernel<<<dim3(QKVW / 128, MTILES), 512, GEMM_SMEM>>>(
        p_a, p_wq, nullptr, nullptr, QKVW, 0);
    ctx_mma_kernel<<<dim3(SEQ / TOKCH, BATCH * HEADS), 256>>>();
    w2_kernel<<<dim3(4, 32), 256>>>(w_out);
    mma_gemm_kernel<<<dim3(DIM / 128, MTILES), 512, GEMM_SMEM>>>(
        p_qh, p_w2, out, b_out, DIM, 1);
}

// round 13
// speedup vs baseline: 1.7831x; 1.0119x over previous
#include <cuda_runtime.h>
#include <cuda_fp16.h>
#include <cstdint>

#define BATCH   4
#define SEQ     8192
#define DIM     512
#define HEADS   8
#define NTOK    32768
#define QKVW    1536
#define SCALE_Q 0.125f
#define MTILES  256
#define PADT    133

// ---------------- scratch ----------------
__device__ __align__(16) __half g_a[(size_t)NTOK * DIM];
__device__ __align__(16) __half g_wq[(size_t)DIM * QKVW];
__device__ __align__(16) __half g_k[(size_t)NTOK * 512];   // head-major [b][h][n][64]
__device__ __align__(16) __half g_v[(size_t)NTOK * 512];   // head-major [b][h][n][64]
__device__ __align__(16) __half g_qh[(size_t)NTOK * 512];  // exp(q*scale) fp16
__device__ __align__(16) __half g_w2[(size_t)BATCH * DIM * DIM]; // per-batch fused ctx@w_out
__device__ float g_ctx[BATCH * HEADS * 64 * 64];
__device__ float g_qsum[BATCH * DIM];

// ---------------- PTX helpers (family-target-safe only) ----------------
__device__ __forceinline__ uint32_t s2u(const void* p) {
    uint32_t a;
    asm("{ .reg .u64 t; cvta.to.shared.u64 t, %1; cvt.u32.u64 %0, t; }" : "=r"(a) : "l"(p));
    return a;
}
#define CP16(d, s)                                                            \
    asm volatile("cp.async.cg.shared.global [%0], [%1], 16;" :: "r"(d), "l"(s) : "memory")
#define CPCOMMIT() asm volatile("cp.async.commit_group;" ::: "memory")
#define CPWAIT1()  asm volatile("cp.async.wait_group 1;" ::: "memory")
#define LDSM_X4(r, a)                                                         \
    asm volatile("ldmatrix.sync.aligned.m8n8.x4.shared.b16 {%0,%1,%2,%3}, [%4];" \
        : "=r"((r)[0]), "=r"((r)[1]), "=r"((r)[2]), "=r"((r)[3]) : "r"(a))
#define LDSM_X4T(r, a)                                                        \
    asm volatile("ldmatrix.sync.aligned.m8n8.x4.trans.shared.b16 {%0,%1,%2,%3}, [%4];" \
        : "=r"((r)[0]), "=r"((r)[1]), "=r"((r)[2]), "=r"((r)[3]) : "r"(a))
#define MMA(d, a, b)                                                          \
    asm volatile("mma.sync.aligned.m16n8k16.row.col.f32.f16.f16.f32 "         \
        "{%0,%1,%2,%3},{%4,%5,%6,%7},{%8,%9},{%0,%1,%2,%3};"                  \
        : "+f"((d)[0]), "+f"((d)[1]), "+f"((d)[2]), "+f"((d)[3])              \
        : "r"((a)[0]), "r"((a)[1]), "r"((a)[2]), "r"((a)[3]),                 \
          "r"((b)[0]), "r"((b)[1]))

// ---------------- init ----------------
__global__ void init_kernel() {
    int i = blockIdx.x * 256 + threadIdx.x;
    if (i < BATCH * HEADS * 64 * 64) g_ctx[i] = 0.f;
    if (i < BATCH * DIM) g_qsum[i] = 0.f;
}

// ---------------- LayerNorm + transpose -> row-major fp16 ------------------
__global__ __launch_bounds__(256) void ln_kernel(
    const float* __restrict__ x, const float* __restrict__ lw,
    const float* __restrict__ lb)
{
    extern __shared__ float s[];               // [512][33]
    __shared__ float s_mu[32], s_rs[32];
    int tid = threadIdx.x;
    int token0 = blockIdx.x * 32;
    int b = token0 >> 13;
    int n0 = token0 & (SEQ - 1);
    const float* xb = x + (size_t)b * DIM * SEQ;

    #pragma unroll 4
    for (int i = 0; i < 64; i++) {
        int idx = i * 256 + tid;
        int d = idx >> 5, j = idx & 31;
        s[d * 33 + j] = xb[(size_t)d * SEQ + n0 + j];
    }
    __syncthreads();

    int w = tid >> 5, lane = tid & 31;
    for (int t = 0; t < 4; t++) {
        int j = w * 4 + t;
        float sum = 0.f, sq = 0.f;
        #pragma unroll
        for (int d = lane; d < DIM; d += 32) {
            float v = s[d * 33 + j];
            sum += v; sq += v * v;
        }
        #pragma unroll
        for (int o = 16; o; o >>= 1) {
            sum += __shfl_xor_sync(0xffffffffu, sum, o);
            sq  += __shfl_xor_sync(0xffffffffu, sq, o);
        }
        if (lane == 0) {
            float mu = sum * (1.f / DIM);
            float var = sq * (1.f / DIM) - mu * mu;
            s_mu[j] = mu;
            s_rs[j] = rsqrtf(var + 1e-5f);
        }
    }
    __syncthreads();

    #pragma unroll
    for (int it = 0; it < 8; it++) {
        int idx = it * 256 + tid;
        int g = idx & 63, j = idx >> 6;
        int d0 = g * 8;
        float mu = s_mu[j], rs = s_rs[j];
        union { __half h[8]; uint4 u; } ph;
        #pragma unroll
        for (int i = 0; i < 8; i++) {
            int d = d0 + i;
            float v = (s[d * 33 + j] - mu) * rs * lw[d] + lb[d];
            ph.h[i] = __float2half_rn(v);
        }
        *(uint4*)&g_a[(size_t)(token0 + j) * DIM + d0] = ph.u;
    }
}

// ---------------- weight fp32 -> fp16 (qkv only) ----------------------------
__global__ __launch_bounds__(256) void wconv_kernel(const float* __restrict__ wq)
{
    int stride = gridDim.x * 256;
    for (int i = blockIdx.x * 256 + threadIdx.x; i < DIM * QKVW; i += stride)
        g_wq[i] = __float2half_rn(wq[i]);
}

// ---------------- fp16 HMMA GEMM: C = A @ B, K=512 --------------------------
// 512 threads, 16 warps in 4x4 grid, 32x32 warp tiles. B via x4.trans ldmatrix.
// mode 0: qkv. q cols -> g_qh fp16 exp + colsums; k/v -> g_k/g_v fp16 head-major.
// mode 1: out[b][dout][n] = qh @ W2_b + bias (B indexed per batch).
#define SLICE 10496              // A 6144 + B 4352
#define STAGE (2 * SLICE)        // 20992
__global__ __launch_bounds__(512, 2) void mma_gemm_kernel(
    const __half* __restrict__ A, const __half* __restrict__ B,
    float* __restrict__ C, const float* __restrict__ bias, int ldb, int mode)
{
    extern __shared__ char smem[];
    uint32_t sb = s2u(smem);
    int tid = threadIdx.x, lane = tid & 31, wid = tid >> 5;
    int m0 = blockIdx.y * 128, n0 = blockIdx.x * 128;
    int wm = (wid >> 2) * 32, wn = (wid & 3) * 32;
    bool loader = (tid < 256);

    if (mode == 1) B += (size_t)(m0 >> 13) * DIM * DIM;   // per-batch W2

    int lt = tid & 255;
    int ar = lt >> 1, ah8 = (lt & 1) * 8;
    int bkr = lt >> 4, bn8 = (lt & 15) * 8;
    const __half* Ag = A + (size_t)(m0 + ar) * DIM + ah8;
    const __half* Bg = B + (size_t)bkr * ldb + n0 + bn8;
    uint32_t dA = sb + ar * 48 + ah8 * 2;
    uint32_t dB = sb + 6144 + bkr * 272 + bn8 * 2;

    uint32_t aAddr[2], bAddr[2];
    #pragma unroll
    for (int mi = 0; mi < 2; mi++)
        aAddr[mi] = sb + (wm + mi * 16 + (lane & 15)) * 48 + (lane >> 4) * 16;
    // B x4.trans: lanes 0-15 rows k0-15 at col (wn + pi*16); lanes 16-31 same rows col +8
    #pragma unroll
    for (int pi = 0; pi < 2; pi++)
        bAddr[pi] = sb + 6144 + (lane & 15) * 272 +
                    (wn + pi * 16 + (lane >> 4) * 8) * 2;

    float d[2][4][4];
    #pragma unroll
    for (int mi = 0; mi < 2; mi++)
        #pragma unroll
        for (int ni = 0; ni < 4; ni++)
            #pragma unroll
            for (int r = 0; r < 4; r++) d[mi][ni][r] = 0.f;

    if (loader) {
        #pragma unroll
        for (int p = 0; p < 2; p++) {
            #pragma unroll
            for (int s = 0; s < 2; s++) {
                uint32_t so = p * STAGE + s * SLICE;
                int ks = p * 2 + s;
                CP16(dA + so, Ag + ks * 16);
                CP16(dB + so, Bg + (size_t)ks * 16 * ldb);
            }
            CPCOMMIT();
        }
    }

    for (int kk = 0; kk < 16; kk++) {
        if (loader) CPWAIT1();
        __syncthreads();
        if (loader) {
            if (kk + 2 < 16) {
                #pragma unroll
                for (int s = 0; s < 2; s++) {
                    uint32_t so = ((kk + 2) % 3) * STAGE + s * SLICE;
                    int ks = (kk + 2) * 2 + s;
                    CP16(dA + so, Ag + ks * 16);
                    CP16(dB + so, Bg + (size_t)ks * 16 * ldb);
                }
            }
            CPCOMMIT();
        }

        #pragma unroll
        for (int s = 0; s < 2; s++) {
            uint32_t so = (kk % 3) * STAGE + s * SLICE;
            uint32_t ah[2][4], bh[2][4];
            #pragma unroll
            for (int mi = 0; mi < 2; mi++)
                LDSM_X4(ah[mi], aAddr[mi] + so);
            #pragma unroll
            for (int pi = 0; pi < 2; pi++)
                LDSM_X4T(bh[pi], bAddr[pi] + so);
            #pragma unroll
            for (int mi = 0; mi < 2; mi++)
                #pragma unroll
                for (int ni = 0; ni < 4; ni++)
                    MMA(d[mi][ni], ah[mi], &bh[ni >> 1][(ni & 1) * 2]);
        }
    }

    if (mode == 0) {
        int region = n0 >> 9;                  // 0: q, 1: k, 2: v
        if (region == 0) {
            float* qs = (float*)smem;
            __syncthreads();
            if (tid < 128) qs[tid] = 0.f;
            __syncthreads();
            #pragma unroll
            for (int mi = 0; mi < 2; mi++) {
                int r0 = m0 + wm + mi * 16 + (lane >> 2);
                #pragma unroll
                for (int ni = 0; ni < 4; ni++) {
                    int cl = wn + ni * 8 + (lane & 3) * 2;
                    float v0 = __expf(d[mi][ni][0] * SCALE_Q);
                    float v1 = __expf(d[mi][ni][1] * SCALE_Q);
                    float v2 = __expf(d[mi][ni][2] * SCALE_Q);
                    float v3 = __expf(d[mi][ni][3] * SCALE_Q);
                    atomicAdd(&qs[cl],     v0 + v2);
                    atomicAdd(&qs[cl + 1], v1 + v3);
                    *(__half2*)&g_qh[(size_t)r0 * 512 + n0 + cl] =
                        __floats2half2_rn(v0, v1);
                    *(__half2*)&g_qh[(size_t)(r0 + 8) * 512 + n0 + cl] =
                        __floats2half2_rn(v2, v3);
                }
            }
            __syncthreads();
            if (tid < 128)
                atomicAdd(&g_qsum[(m0 >> 13) * DIM + n0 + tid], qs[tid]);
        } else {
            __half* dstbuf = (region == 1) ? g_k : g_v;
            int colbase = n0 & 511;
            #pragma unroll
            for (int mi = 0; mi < 2; mi++) {
                int r0 = m0 + wm + mi * 16 + (lane >> 2);
                int b = r0 >> 13, n = r0 & (SEQ - 1);
                #pragma unroll
                for (int ni = 0; ni < 4; ni++) {
                    int col = colbase + wn + ni * 8 + (lane & 3) * 2;
                    int h = col >> 6, dd = col & 63;
                    size_t base = ((size_t)(b * HEADS + h) * SEQ + n) * 64 + dd;
                    *(__half2*)&dstbuf[base] =
                        __floats2half2_rn(d[mi][ni][0], d[mi][ni][1]);
                    *(__half2*)&dstbuf[base + 8 * 64] =
                        __floats2half2_rn(d[mi][ni][2], d[mi][ni][3]);
                }
            }
        }
    } else {
        __syncthreads();
        float* st = (float*)smem;             // [128][PADT]
        #pragma unroll
        for (int mi = 0; mi < 2; mi++) {
            int r0 = wm + mi * 16 + (lane >> 2);
            #pragma unroll
            for (int ni = 0; ni < 4; ni++) {
                int c0 = wn + ni * 8 + (lane & 3) * 2;
                st[r0 * PADT + c0]           = d[mi][ni][0];
                st[r0 * PADT + c0 + 1]       = d[mi][ni][1];
                st[(r0 + 8) * PADT + c0]     = d[mi][ni][2];
                st[(r0 + 8) * PADT + c0 + 1] = d[mi][ni][3];
            }
        }
        __syncthreads();
        int b = m0 >> 13, nn0 = m0 & (SEQ - 1);
        float* dst = C + (size_t)b * DIM * SEQ + (size_t)n0 * SEQ + nn0;
        for (int idx = tid; idx < 16384; idx += 512) {
            int r = idx >> 7;
            int c = idx & 127;
            dst[(size_t)r * SEQ + c] = st[c * PADT + r] + bias[n0 + r];
        }
    }
}

// ---------------- ctx = softmax_d(k)^T @ v per (b,h) on tensor cores --------
// grid (SEQ/1024, 32 bh), 256 threads, 8 warps: 16x32 warp tiles over 64x64.
#define TOKCH 1024
#define SUBT  128
#define KTP   72                 // padded row stride in halfs (144B)
__global__ __launch_bounds__(256) void ctx_mma_kernel()
{
    __shared__ __half kt[SUBT * KTP];
    __shared__ __half vt[SUBT * KTP];
    int tid = threadIdx.x, lane = tid & 31, wid = tid >> 5;
    int bh = blockIdx.y;
    int tok0 = blockIdx.x * TOKCH;
    const __half* kbase = g_k + (size_t)bh * SEQ * 64;
    const __half* vbase = g_v + (size_t)bh * SEQ * 64;

    int wm = (wid & 3) * 16, wn = (wid >> 2) * 32;
    // A (k-hat^T) trans-ldmatrix lane address
    int l7 = lane & 7, sel = lane >> 3;
    uint32_t aBase = s2u(kt) + (uint32_t)((((sel >> 1) * 8) + l7) * KTP + wm + (sel & 1) * 8) * 2;
    // B x4.trans: lanes 0-15 rows k0-15 at col (wn + pi*16); lanes 16-31 col +8
    uint32_t bBase[2];
    #pragma unroll
    for (int pi = 0; pi < 2; pi++)
        bBase[pi] = s2u(vt) + (uint32_t)((lane & 15) * KTP + wn + pi * 16 +
                                         (lane >> 4) * 8) * 2;

    float acc[4][4] = {};
    int t = tid >> 1, h4 = tid & 1;

    for (int st0 = 0; st0 < TOKCH; st0 += SUBT) {
        const uint4* kr4 = (const uint4*)(kbase + (size_t)(tok0 + st0 + t) * 64 + h4 * 32);
        uint4 kr[4];
        #pragma unroll
        for (int i = 0; i < 4; i++) kr[i] = kr4[i];
        float e[32];
        float s = 0.f;
        #pragma unroll
        for (int i = 0; i < 4; i++) {
            const __half2* hp = (const __half2*)&kr[i];
            #pragma unroll
            for (int j = 0; j < 4; j++) {
                float2 f = __half22float2(hp[j]);
                float e0 = __expf(f.x), e1 = __expf(f.y);
                e[i * 8 + j * 2] = e0;
                e[i * 8 + j * 2 + 1] = e1;
                s += e0 + e1;
            }
        }
        s += __shfl_xor_sync(0xffffffffu, s, 1);
        float inv = 1.f / s;
        #pragma unroll
        for (int i = 0; i < 4; i++) {
            uint4 kw;
            __half2* op = (__half2*)&kw;
            #pragma unroll
            for (int j = 0; j < 4; j++)
                op[j] = __floats2half2_rn(e[i * 8 + j * 2] * inv,
                                          e[i * 8 + j * 2 + 1] * inv);
            *(uint4*)&kt[t * KTP + h4 * 32 + i * 8] = kw;
        }
        const uint4* vr4 = (const uint4*)(vbase + (size_t)(tok0 + st0 + t) * 64 + h4 * 32);
        #pragma unroll
        for (int i = 0; i < 4; i++)
            *(uint4*)&vt[t * KTP + h4 * 32 + i * 8] = vr4[i];
        __syncthreads();

        #pragma unroll
        for (int k16 = 0; k16 < SUBT; k16 += 16) {
            uint32_t a[4];
            LDSM_X4T(a, aBase + (uint32_t)k16 * (KTP * 2));
            #pragma unroll
            for (int pi = 0; pi < 2; pi++) {
                uint32_t bb[4];
                LDSM_X4T(bb, bBase[pi] + (uint32_t)k16 * (KTP * 2));
                MMA(acc[pi * 2],     a, &bb[0]);
                MMA(acc[pi * 2 + 1], a, &bb[2]);
            }
        }
        __syncthreads();
    }

    float* cb = g_ctx + (size_t)bh * 4096;
    int r = wm + (lane >> 2);
    #pragma unroll
    for (int ni = 0; ni < 4; ni++) {
        int c = wn + ni * 8 + (lane & 3) * 2;
        atomicAdd(&cb[r * 64 + c],           acc[ni][0]);
        atomicAdd(&cb[r * 64 + c + 1],       acc[ni][1]);
        atomicAdd(&cb[(r + 8) * 64 + c],     acc[ni][2]);
        atomicAdd(&cb[(r + 8) * 64 + c + 1], acc[ni][3]);
    }
}

// ---------------- W2_b = vstack_h( diag(rq_h) * (ctx_bh @ w_out_h) ) --------
__global__ __launch_bounds__(256) void w2_kernel(const float* __restrict__ w_out)
{
    __shared__ float cs[64][65];
    __shared__ float ws[64][128];
    int tid = threadIdx.x;
    int jc = blockIdx.x;                   // 128-wide output column chunk
    int bh = blockIdx.y;
    int b = bh >> 3, h = bh & 7;

    const float* csrc = g_ctx + (size_t)bh * 4096;
    for (int i = tid; i < 4096; i += 256) cs[i >> 6][i & 63] = csrc[i];
    for (int i = tid; i < 64 * 128; i += 256) {
        int e = i >> 7, j = i & 127;
        ws[e][j] = w_out[(size_t)(h * 64 + e) * DIM + jc * 128 + j];
    }
    __syncthreads();

    int dd = tid >> 2, j0 = (tid & 3) * 32;
    float rq = 1.f / g_qsum[b * DIM + h * 64 + dd];
    float acc[32] = {};
    #pragma unroll 8
    for (int e = 0; e < 64; e++) {
        float a = cs[dd][e];
        #pragma unroll
        for (int j = 0; j < 32; j++) acc[j] += a * ws[e][j0 + j];
    }
    __half* dst = g_w2 + ((size_t)b * DIM + h * 64 + dd) * DIM + jc * 128 + j0;
    #pragma unroll
    for (int j = 0; j < 32; j += 2)
        *(__half2*)&dst[j] = __floats2half2_rn(acc[j] * rq, acc[j + 1] * rq);
}

// ---------------- launch ------------------------------------------------------
extern "C" void kernel_launch(void* const* d_in, const int* in_sizes, int n_in,
                              void* d_out, int out_size)
{
    const float* x     = (const float*)d_in[0];
    const float* ln_w  = (const float*)d_in[1];
    const float* ln_b  = (const float*)d_in[2];
    const float* w_qkv = (const float*)d_in[3];
    const float* w_out = (const float*)d_in[4];
    const float* b_out = (const float*)d_in[5];
    float* out = (float*)d_out;

    __half *p_a, *p_wq, *p_qh, *p_w2;
    cudaGetSymbolAddress((void**)&p_a, g_a);
    cudaGetSymbolAddress((void**)&p_wq, g_wq);
    cudaGetSymbolAddress((void**)&p_qh, g_qh);
    cudaGetSymbolAddress((void**)&p_w2, g_w2);

    const int LN_SMEM   = 512 * 33 * 4;
    const int GEMM_SMEM = 128 * PADT * 4;    // 68096 >= 3*STAGE = 62976
    cudaFuncSetAttribute(ln_kernel, cudaFuncAttributeMaxDynamicSharedMemorySize, LN_SMEM);
    cudaFuncSetAttribute(mma_gemm_kernel, cudaFuncAttributeMaxDynamicSharedMemorySize, GEMM_SMEM);

    init_kernel<<<(BATCH * HEADS * 64 * 64 + 255) / 256, 256>>>();
    ln_kernel<<<NTOK / 32, 256, LN_SMEM>>>(x, ln_w, ln_b);
    wconv_kernel<<<768, 256>>>(w_qkv);
    mma_gemm_kernel<<<dim3(QKVW / 128, MTILES), 512, GEMM_SMEM>>>(
        p_a, p_wq, nullptr, nullptr, QKVW, 0);
    ctx_mma_kernel<<<dim3(SEQ / TOKCH, BATCH * HEADS), 256>>>();
    w2_kernel<<<dim3(4, 32), 256>>>(w_out);
    mma_gemm_kernel<<<dim3(DIM / 128, MTILES), 512, GEMM_SMEM>>>(
        p_qh, p_w2, out, b_out, DIM, 1);
}

// round 14
// speedup vs baseline: 1.8093x; 1.0146x over previous
#include <cuda_runtime.h>
#include <cuda_fp16.h>
#include <cstdint>

#define BATCH   4
#define SEQ     8192
#define DIM     512
#define HEADS   8
#define NTOK    32768
#define QKVW    1536
#define SCALE_Q 0.125f
#define MTILES  256
#define PADT    133

// ---------------- scratch ----------------
__device__ __align__(16) __half g_a[(size_t)NTOK * DIM];
__device__ __align__(16) __half g_wq[(size_t)DIM * QKVW];
__device__ __align__(16) __half g_k[(size_t)NTOK * 512];   // head-major [b][h][n][64]
__device__ __align__(16) __half g_v[(size_t)NTOK * 512];   // head-major [b][h][n][64]
__device__ __align__(16) __half g_qh[(size_t)NTOK * 512];  // exp(q*scale) fp16
__device__ __align__(16) __half g_w2[(size_t)BATCH * DIM * DIM]; // per-batch fused ctx@w_out
__device__ float g_ctx[BATCH * HEADS * 64 * 64];
__device__ float g_qsum[BATCH * DIM];

// ---------------- PTX helpers (family-target-safe only) ----------------
__device__ __forceinline__ uint32_t s2u(const void* p) {
    uint32_t a;
    asm("{ .reg .u64 t; cvta.to.shared.u64 t, %1; cvt.u32.u64 %0, t; }" : "=r"(a) : "l"(p));
    return a;
}
#define CP16(d, s)                                                            \
    asm volatile("cp.async.cg.shared.global [%0], [%1], 16;" :: "r"(d), "l"(s) : "memory")
#define CPCOMMIT() asm volatile("cp.async.commit_group;" ::: "memory")
#define CPWAIT2()  asm volatile("cp.async.wait_group 2;" ::: "memory")
#define LDSM_X4(r, a)                                                         \
    asm volatile("ldmatrix.sync.aligned.m8n8.x4.shared.b16 {%0,%1,%2,%3}, [%4];" \
        : "=r"((r)[0]), "=r"((r)[1]), "=r"((r)[2]), "=r"((r)[3]) : "r"(a))
#define LDSM_X4T(r, a)                                                        \
    asm volatile("ldmatrix.sync.aligned.m8n8.x4.trans.shared.b16 {%0,%1,%2,%3}, [%4];" \
        : "=r"((r)[0]), "=r"((r)[1]), "=r"((r)[2]), "=r"((r)[3]) : "r"(a))
#define MMA(d, a, b)                                                          \
    asm volatile("mma.sync.aligned.m16n8k16.row.col.f32.f16.f16.f32 "         \
        "{%0,%1,%2,%3},{%4,%5,%6,%7},{%8,%9},{%0,%1,%2,%3};"                  \
        : "+f"((d)[0]), "+f"((d)[1]), "+f"((d)[2]), "+f"((d)[3])              \
        : "r"((a)[0]), "r"((a)[1]), "r"((a)[2]), "r"((a)[3]),                 \
          "r"((b)[0]), "r"((b)[1]))

// ---------------- weight fp32 -> fp16 + zero accumulators -------------------
__global__ __launch_bounds__(256) void wconv_kernel(const float* __restrict__ wq)
{
    int gid = blockIdx.x * 256 + threadIdx.x;
    int stride = gridDim.x * 256;
    for (int i = gid; i < DIM * QKVW; i += stride)
        g_wq[i] = __float2half_rn(wq[i]);
    if (gid < BATCH * HEADS * 64 * 64) g_ctx[gid] = 0.f;
    if (gid < BATCH * DIM) g_qsum[gid] = 0.f;
}

// ---------------- LayerNorm + transpose -> row-major fp16 (fp16 staging) ----
__global__ __launch_bounds__(256) void ln_kernel(
    const float* __restrict__ x, const float* __restrict__ lw,
    const float* __restrict__ lb)
{
    extern __shared__ __half s[];               // [512][33] halfs = 33792 B
    __shared__ float s_mu[32], s_rs[32];
    int tid = threadIdx.x;
    int token0 = blockIdx.x * 32;
    int b = token0 >> 13;
    int n0 = token0 & (SEQ - 1);
    const float* xb = x + (size_t)b * DIM * SEQ;

    #pragma unroll 4
    for (int i = 0; i < 64; i++) {
        int idx = i * 256 + tid;
        int d = idx >> 5, j = idx & 31;
        s[d * 33 + j] = __float2half_rn(xb[(size_t)d * SEQ + n0 + j]);
    }
    __syncthreads();

    int w = tid >> 5, lane = tid & 31;
    for (int t = 0; t < 4; t++) {
        int j = w * 4 + t;
        float sum = 0.f, sq = 0.f;
        #pragma unroll
        for (int d = lane; d < DIM; d += 32) {
            float v = __half2float(s[d * 33 + j]);
            sum += v; sq += v * v;
        }
        #pragma unroll
        for (int o = 16; o; o >>= 1) {
            sum += __shfl_xor_sync(0xffffffffu, sum, o);
            sq  += __shfl_xor_sync(0xffffffffu, sq, o);
        }
        if (lane == 0) {
            float mu = sum * (1.f / DIM);
            float var = sq * (1.f / DIM) - mu * mu;
            s_mu[j] = mu;
            s_rs[j] = rsqrtf(var + 1e-5f);
        }
    }
    __syncthreads();

    #pragma unroll
    for (int it = 0; it < 8; it++) {
        int idx = it * 256 + tid;
        int g = idx & 63, j = idx >> 6;
        int d0 = g * 8;
        float mu = s_mu[j], rs = s_rs[j];
        union { __half h[8]; uint4 u; } ph;
        #pragma unroll
        for (int i = 0; i < 8; i++) {
            int d = d0 + i;
            float v = (__half2float(s[d * 33 + j]) - mu) * rs * lw[d] + lb[d];
            ph.h[i] = __float2half_rn(v);
        }
        *(uint4*)&g_a[(size_t)(token0 + j) * DIM + d0] = ph.u;
    }
}

// ---------------- fp16 HMMA GEMM: C = A @ B, K=512 --------------------------
// 512 threads, 16 warps in 4x4 grid, 32x32 warp tiles. 4-stage cp.async
// pipeline (BK=32 per stage, wait_group 2 => prefetch distance 3).
// mode 0: qkv. q cols -> g_qh fp16 exp + colsums; k/v -> g_k/g_v fp16 head-major.
// mode 1: out[b][dout][n] = qh @ W2_b + bias (B indexed per batch).
#define SLICE 10496              // A 6144 + B 4352
#define STAGE (2 * SLICE)        // 20992
__global__ __launch_bounds__(512, 2) void mma_gemm_kernel(
    const __half* __restrict__ A, const __half* __restrict__ B,
    float* __restrict__ C, const float* __restrict__ bias, int ldb, int mode)
{
    extern __shared__ char smem[];
    uint32_t sb = s2u(smem);
    int tid = threadIdx.x, lane = tid & 31, wid = tid >> 5;
    int m0 = blockIdx.y * 128, n0 = blockIdx.x * 128;
    int wm = (wid >> 2) * 32, wn = (wid & 3) * 32;
    bool loader = (tid < 256);

    if (mode == 1) B += (size_t)(m0 >> 13) * DIM * DIM;   // per-batch W2

    int lt = tid & 255;
    int ar = lt >> 1, ah8 = (lt & 1) * 8;
    int bkr = lt >> 4, bn8 = (lt & 15) * 8;
    const __half* Ag = A + (size_t)(m0 + ar) * DIM + ah8;
    const __half* Bg = B + (size_t)bkr * ldb + n0 + bn8;
    uint32_t dA = sb + ar * 48 + ah8 * 2;
    uint32_t dB = sb + 6144 + bkr * 272 + bn8 * 2;

    uint32_t aAddr[2], bAddr[2];
    #pragma unroll
    for (int mi = 0; mi < 2; mi++)
        aAddr[mi] = sb + (wm + mi * 16 + (lane & 15)) * 48 + (lane >> 4) * 16;
    #pragma unroll
    for (int pi = 0; pi < 2; pi++)
        bAddr[pi] = sb + 6144 + (lane & 15) * 272 +
                    (wn + pi * 16 + (lane >> 4) * 8) * 2;

    float d[2][4][4];
    #pragma unroll
    for (int mi = 0; mi < 2; mi++)
        #pragma unroll
        for (int ni = 0; ni < 4; ni++)
            #pragma unroll
            for (int r = 0; r < 4; r++) d[mi][ni][r] = 0.f;

    if (loader) {
        #pragma unroll
        for (int p = 0; p < 3; p++) {
            #pragma unroll
            for (int s = 0; s < 2; s++) {
                uint32_t so = p * STAGE + s * SLICE;
                int ks = p * 2 + s;
                CP16(dA + so, Ag + ks * 16);
                CP16(dB + so, Bg + (size_t)ks * 16 * ldb);
            }
            CPCOMMIT();
        }
    }

    for (int kk = 0; kk < 16; kk++) {
        if (loader) CPWAIT2();
        __syncthreads();
        if (loader) {
            if (kk + 3 < 16) {
                #pragma unroll
                for (int s = 0; s < 2; s++) {
                    uint32_t so = ((kk + 3) & 3) * STAGE + s * SLICE;
                    int ks = (kk + 3) * 2 + s;
                    CP16(dA + so, Ag + ks * 16);
                    CP16(dB + so, Bg + (size_t)ks * 16 * ldb);
                }
            }
            CPCOMMIT();
        }

        #pragma unroll
        for (int s = 0; s < 2; s++) {
            uint32_t so = (kk & 3) * STAGE + s * SLICE;
            uint32_t ah[2][4], bh[2][4];
            #pragma unroll
            for (int mi = 0; mi < 2; mi++)
                LDSM_X4(ah[mi], aAddr[mi] + so);
            #pragma unroll
            for (int pi = 0; pi < 2; pi++)
                LDSM_X4T(bh[pi], bAddr[pi] + so);
            #pragma unroll
            for (int mi = 0; mi < 2; mi++)
                #pragma unroll
                for (int ni = 0; ni < 4; ni++)
                    MMA(d[mi][ni], ah[mi], &bh[ni >> 1][(ni & 1) * 2]);
        }
    }

    if (mode == 0) {
        int region = n0 >> 9;                  // 0: q, 1: k, 2: v
        if (region == 0) {
            float* qs = (float*)smem;
            __syncthreads();
            if (tid < 128) qs[tid] = 0.f;
            __syncthreads();
            #pragma unroll
            for (int mi = 0; mi < 2; mi++) {
                int r0 = m0 + wm + mi * 16 + (lane >> 2);
                #pragma unroll
                for (int ni = 0; ni < 4; ni++) {
                    int cl = wn + ni * 8 + (lane & 3) * 2;
                    float v0 = __expf(d[mi][ni][0] * SCALE_Q);
                    float v1 = __expf(d[mi][ni][1] * SCALE_Q);
                    float v2 = __expf(d[mi][ni][2] * SCALE_Q);
                    float v3 = __expf(d[mi][ni][3] * SCALE_Q);
                    atomicAdd(&qs[cl],     v0 + v2);
                    atomicAdd(&qs[cl + 1], v1 + v3);
                    *(__half2*)&g_qh[(size_t)r0 * 512 + n0 + cl] =
                        __floats2half2_rn(v0, v1);
                    *(__half2*)&g_qh[(size_t)(r0 + 8) * 512 + n0 + cl] =
                        __floats2half2_rn(v2, v3);
                }
            }
            __syncthreads();
            if (tid < 128)
                atomicAdd(&g_qsum[(m0 >> 13) * DIM + n0 + tid], qs[tid]);
        } else {
            __half* dstbuf = (region == 1) ? g_k : g_v;
            int colbase = n0 & 511;
            #pragma unroll
            for (int mi = 0; mi < 2; mi++) {
                int r0 = m0 + wm + mi * 16 + (lane >> 2);
                int b = r0 >> 13, n = r0 & (SEQ - 1);
                #pragma unroll
                for (int ni = 0; ni < 4; ni++) {
                    int col = colbase + wn + ni * 8 + (lane & 3) * 2;
                    int h = col >> 6, dd = col & 63;
                    size_t base = ((size_t)(b * HEADS + h) * SEQ + n) * 64 + dd;
                    *(__half2*)&dstbuf[base] =
                        __floats2half2_rn(d[mi][ni][0], d[mi][ni][1]);
                    *(__half2*)&dstbuf[base + 8 * 64] =
                        __floats2half2_rn(d[mi][ni][2], d[mi][ni][3]);
                }
            }
        }
    } else {
        __syncthreads();
        float* st = (float*)smem;             // [128][PADT]
        #pragma unroll
        for (int mi = 0; mi < 2; mi++) {
            int r0 = wm + mi * 16 + (lane >> 2);
            #pragma unroll
            for (int ni = 0; ni < 4; ni++) {
                int c0 = wn + ni * 8 + (lane & 3) * 2;
                st[r0 * PADT + c0]           = d[mi][ni][0];
                st[r0 * PADT + c0 + 1]       = d[mi][ni][1];
                st[(r0 + 8) * PADT + c0]     = d[mi][ni][2];
                st[(r0 + 8) * PADT + c0 + 1] = d[mi][ni][3];
            }
        }
        __syncthreads();
        int b = m0 >> 13, nn0 = m0 & (SEQ - 1);
        float* dst = C + (size_t)b * DIM * SEQ + (size_t)n0 * SEQ + nn0;
        for (int idx = tid; idx < 16384; idx += 512) {
            int r = idx >> 7;
            int c = idx & 127;
            dst[(size_t)r * SEQ + c] = st[c * PADT + r] + bias[n0 + r];
        }
    }
}

// ---------------- ctx = softmax_d(k)^T @ v per (b,h) on tensor cores --------
#define TOKCH 1024
#define SUBT  128
#define KTP   72                 // padded row stride in halfs (144B)
__global__ __launch_bounds__(256) void ctx_mma_kernel()
{
    __shared__ __half kt[SUBT * KTP];
    __shared__ __half vt[SUBT * KTP];
    int tid = threadIdx.x, lane = tid & 31, wid = tid >> 5;
    int bh = blockIdx.y;
    int tok0 = blockIdx.x * TOKCH;
    const __half* kbase = g_k + (size_t)bh * SEQ * 64;
    const __half* vbase = g_v + (size_t)bh * SEQ * 64;

    int wm = (wid & 3) * 16, wn = (wid >> 2) * 32;
    int l7 = lane & 7, sel = lane >> 3;
    uint32_t aBase = s2u(kt) + (uint32_t)((((sel >> 1) * 8) + l7) * KTP + wm + (sel & 1) * 8) * 2;
    uint32_t bBase[2];
    #pragma unroll
    for (int pi = 0; pi < 2; pi++)
        bBase[pi] = s2u(vt) + (uint32_t)((lane & 15) * KTP + wn + pi * 16 +
                                         (lane >> 4) * 8) * 2;

    float acc[4][4] = {};
    int t = tid >> 1, h4 = tid & 1;

    for (int st0 = 0; st0 < TOKCH; st0 += SUBT) {
        const uint4* kr4 = (const uint4*)(kbase + (size_t)(tok0 + st0 + t) * 64 + h4 * 32);
        uint4 kr[4];
        #pragma unroll
        for (int i = 0; i < 4; i++) kr[i] = kr4[i];
        float e[32];
        float s = 0.f;
        #pragma unroll
        for (int i = 0; i < 4; i++) {
            const __half2* hp = (const __half2*)&kr[i];
            #pragma unroll
            for (int j = 0; j < 4; j++) {
                float2 f = __half22float2(hp[j]);
                float e0 = __expf(f.x), e1 = __expf(f.y);
                e[i * 8 + j * 2] = e0;
                e[i * 8 + j * 2 + 1] = e1;
                s += e0 + e1;
            }
        }
        s += __shfl_xor_sync(0xffffffffu, s, 1);
        float inv = 1.f / s;
        #pragma unroll
        for (int i = 0; i < 4; i++) {
            uint4 kw;
            __half2* op = (__half2*)&kw;
            #pragma unroll
            for (int j = 0; j < 4; j++)
                op[j] = __floats2half2_rn(e[i * 8 + j * 2] * inv,
                                          e[i * 8 + j * 2 + 1] * inv);
            *(uint4*)&kt[t * KTP + h4 * 32 + i * 8] = kw;
        }
        const uint4* vr4 = (const uint4*)(vbase + (size_t)(tok0 + st0 + t) * 64 + h4 * 32);
        #pragma unroll
        for (int i = 0; i < 4; i++)
            *(uint4*)&vt[t * KTP + h4 * 32 + i * 8] = vr4[i];
        __syncthreads();

        #pragma unroll
        for (int k16 = 0; k16 < SUBT; k16 += 16) {
            uint32_t a[4];
            LDSM_X4T(a, aBase + (uint32_t)k16 * (KTP * 2));
            #pragma unroll
            for (int pi = 0; pi < 2; pi++) {
                uint32_t bb[4];
                LDSM_X4T(bb, bBase[pi] + (uint32_t)k16 * (KTP * 2));
                MMA(acc[pi * 2],     a, &bb[0]);
                MMA(acc[pi * 2 + 1], a, &bb[2]);
            }
        }
        __syncthreads();
    }

    float* cb = g_ctx + (size_t)bh * 4096;
    int r = wm + (lane >> 2);
    #pragma unroll
    for (int ni = 0; ni < 4; ni++) {
        int c = wn + ni * 8 + (lane & 3) * 2;
        atomicAdd(&cb[r * 64 + c],           acc[ni][0]);
        atomicAdd(&cb[r * 64 + c + 1],       acc[ni][1]);
        atomicAdd(&cb[(r + 8) * 64 + c],     acc[ni][2]);
        atomicAdd(&cb[(r + 8) * 64 + c + 1], acc[ni][3]);
    }
}

// ---------------- W2_b = vstack_h( diag(rq_h) * (ctx_bh @ w_out_h) ) --------
__global__ __launch_bounds__(256) void w2_kernel(const float* __restrict__ w_out)
{
    __shared__ float cs[64][65];
    __shared__ float ws[64][128];
    int tid = threadIdx.x;
    int jc = blockIdx.x;
    int bh = blockIdx.y;
    int b = bh >> 3, h = bh & 7;

    const float* csrc = g_ctx + (size_t)bh * 4096;
    for (int i = tid; i < 4096; i += 256) cs[i >> 6][i & 63] = csrc[i];
    for (int i = tid; i < 64 * 128; i += 256) {
        int e = i >> 7, j = i & 127;
        ws[e][j] = w_out[(size_t)(h * 64 + e) * DIM + jc * 128 + j];
    }
    __syncthreads();

    int dd = tid >> 2, j0 = (tid & 3) * 32;
    float rq = 1.f / g_qsum[b * DIM + h * 64 + dd];
    float acc[32] = {};
    #pragma unroll 8
    for (int e = 0; e < 64; e++) {
        float a = cs[dd][e];
        #pragma unroll
        for (int j = 0; j < 32; j++) acc[j] += a * ws[e][j0 + j];
    }
    __half* dst = g_w2 + ((size_t)b * DIM + h * 64 + dd) * DIM + jc * 128 + j0;
    #pragma unroll
    for (int j = 0; j < 32; j += 2)
        *(__half2*)&dst[j] = __floats2half2_rn(acc[j] * rq, acc[j + 1] * rq);
}

// ---------------- launch ------------------------------------------------------
extern "C" void kernel_launch(void* const* d_in, const int* in_sizes, int n_in,
                              void* d_out, int out_size)
{
    const float* x     = (const float*)d_in[0];
    const float* ln_w  = (const float*)d_in[1];
    const float* ln_b  = (const float*)d_in[2];
    const float* w_qkv = (const float*)d_in[3];
    const float* w_out = (const float*)d_in[4];
    const float* b_out = (const float*)d_in[5];
    float* out = (float*)d_out;

    __half *p_a, *p_wq, *p_qh, *p_w2;
    cudaGetSymbolAddress((void**)&p_a, g_a);
    cudaGetSymbolAddress((void**)&p_wq, g_wq);
    cudaGetSymbolAddress((void**)&p_qh, g_qh);
    cudaGetSymbolAddress((void**)&p_w2, g_w2);

    const int LN_SMEM   = 512 * 33 * 2;      // 33792 (fp16 staging)
    const int GEMM_SMEM = 4 * STAGE;         // 83968 >= epilogue 68096
    cudaFuncSetAttribute(ln_kernel, cudaFuncAttributeMaxDynamicSharedMemorySize, LN_SMEM);
    cudaFuncSetAttribute(mma_gemm_kernel, cudaFuncAttributeMaxDynamicSharedMemorySize, GEMM_SMEM);

    wconv_kernel<<<768, 256>>>(w_qkv);
    ln_kernel<<<NTOK / 32, 256, LN_SMEM>>>(x, ln_w, ln_b);
    mma_gemm_kernel<<<dim3(QKVW / 128, MTILES), 512, GEMM_SMEM>>>(
        p_a, p_wq, nullptr, nullptr, QKVW, 0);
    ctx_mma_kernel<<<dim3(SEQ / TOKCH, BATCH * HEADS), 256>>>();
    w2_kernel<<<dim3(4, 32), 256>>>(w_out);
    mma_gemm_kernel<<<dim3(DIM / 128, MTILES), 512, GEMM_SMEM>>>(
        p_qh, p_w2, out, b_out, DIM, 1);
}

// round 16
// speedup vs baseline: 1.8140x; 1.0026x over previous
#include <cuda_runtime.h>
#include <cuda_fp16.h>
#include <cstdint>

#define BATCH   4
#define SEQ     8192
#define DIM     512
#define HEADS   8
#define NTOK    32768
#define QKVW    1536
#define SCALE_Q 0.125f
#define MTILES  256
#define PADT    133

// ---------------- scratch ----------------
__device__ __align__(16) __half g_a[(size_t)NTOK * DIM];
__device__ __align__(16) __half g_wq[(size_t)DIM * QKVW];
__device__ __align__(16) __half g_k[(size_t)NTOK * 512];   // head-major [b][h][n][64]
__device__ __align__(16) __half g_v[(size_t)NTOK * 512];   // head-major [b][h][n][64]
__device__ __align__(16) __half g_qh[(size_t)NTOK * 512];  // exp(q*scale) fp16
__device__ __align__(16) __half g_w2[(size_t)BATCH * DIM * DIM]; // per-batch fused ctx@w_out
__device__ float g_ctx[BATCH * HEADS * 64 * 64];
__device__ float g_qsum[BATCH * DIM];

// ---------------- PTX helpers (family-target-safe only) ----------------
__device__ __forceinline__ uint32_t s2u(const void* p) {
    uint32_t a;
    asm("{ .reg .u64 t; cvta.to.shared.u64 t, %1; cvt.u32.u64 %0, t; }" : "=r"(a) : "l"(p));
    return a;
}
#define CP16(d, s)                                                            \
    asm volatile("cp.async.cg.shared.global [%0], [%1], 16;" :: "r"(d), "l"(s) : "memory")
#define CPCOMMIT() asm volatile("cp.async.commit_group;" ::: "memory")
#define CPWAIT2()  asm volatile("cp.async.wait_group 2;" ::: "memory")
#define LDSM_X4(r, a)                                                         \
    asm volatile("ldmatrix.sync.aligned.m8n8.x4.shared.b16 {%0,%1,%2,%3}, [%4];" \
        : "=r"((r)[0]), "=r"((r)[1]), "=r"((r)[2]), "=r"((r)[3]) : "r"(a))
#define LDSM_X4T(r, a)                                                        \
    asm volatile("ldmatrix.sync.aligned.m8n8.x4.trans.shared.b16 {%0,%1,%2,%3}, [%4];" \
        : "=r"((r)[0]), "=r"((r)[1]), "=r"((r)[2]), "=r"((r)[3]) : "r"(a))
#define MMA(d, a, b)                                                          \
    asm volatile("mma.sync.aligned.m16n8k16.row.col.f32.f16.f16.f32 "         \
        "{%0,%1,%2,%3},{%4,%5,%6,%7},{%8,%9},{%0,%1,%2,%3};"                  \
        : "+f"((d)[0]), "+f"((d)[1]), "+f"((d)[2]), "+f"((d)[3])              \
        : "r"((a)[0]), "r"((a)[1]), "r"((a)[2]), "r"((a)[3]),                 \
          "r"((b)[0]), "r"((b)[1]))

// ---------------- weight fp32 -> fp16 + zero accumulators -------------------
__global__ __launch_bounds__(256) void wconv_kernel(const float* __restrict__ wq)
{
    int gid = blockIdx.x * 256 + threadIdx.x;
    int stride = gridDim.x * 256;
    for (int i = gid; i < DIM * QKVW; i += stride)
        g_wq[i] = __float2half_rn(wq[i]);
    if (gid < BATCH * HEADS * 64 * 64) g_ctx[gid] = 0.f;
    if (gid < BATCH * DIM) g_qsum[gid] = 0.f;
}

// ---------------- LayerNorm + transpose -> row-major fp16 (fp16 staging) ----
__global__ __launch_bounds__(256) void ln_kernel(
    const float* __restrict__ x, const float* __restrict__ lw,
    const float* __restrict__ lb)
{
    extern __shared__ __half s[];               // [512][33] halfs = 33792 B
    __shared__ float s_mu[32], s_rs[32];
    int tid = threadIdx.x;
    int token0 = blockIdx.x * 32;
    int b = token0 >> 13;
    int n0 = token0 & (SEQ - 1);
    const float* xb = x + (size_t)b * DIM * SEQ;

    #pragma unroll 4
    for (int i = 0; i < 64; i++) {
        int idx = i * 256 + tid;
        int d = idx >> 5, j = idx & 31;
        s[d * 33 + j] = __float2half_rn(xb[(size_t)d * SEQ + n0 + j]);
    }
    __syncthreads();

    int w = tid >> 5, lane = tid & 31;
    for (int t = 0; t < 4; t++) {
        int j = w * 4 + t;
        float sum = 0.f, sq = 0.f;
        #pragma unroll
        for (int d = lane; d < DIM; d += 32) {
            float v = __half2float(s[d * 33 + j]);
            sum += v; sq += v * v;
        }
        #pragma unroll
        for (int o = 16; o; o >>= 1) {
            sum += __shfl_xor_sync(0xffffffffu, sum, o);
            sq  += __shfl_xor_sync(0xffffffffu, sq, o);
        }
        if (lane == 0) {
            float mu = sum * (1.f / DIM);
            float var = sq * (1.f / DIM) - mu * mu;
            s_mu[j] = mu;
            s_rs[j] = rsqrtf(var + 1e-5f);
        }
    }
    __syncthreads();

    #pragma unroll
    for (int it = 0; it < 8; it++) {
        int idx = it * 256 + tid;
        int g = idx & 63, j = idx >> 6;
        int d0 = g * 8;
        float mu = s_mu[j], rs = s_rs[j];
        union { __half h[8]; uint4 u; } ph;
        #pragma unroll
        for (int i = 0; i < 8; i++) {
            int d = d0 + i;
            float v = (__half2float(s[d * 33 + j]) - mu) * rs * lw[d] + lb[d];
            ph.h[i] = __float2half_rn(v);
        }
        *(uint4*)&g_a[(size_t)(token0 + j) * DIM + d0] = ph.u;
    }
}

// ---------------- fp16 HMMA GEMM: C = A @ B, K=512 --------------------------
// 512 threads, 16 warps in 4x4 grid, 32x32 warp tiles. 4-stage cp.async
// pipeline (BK=32 per stage, wait_group 2 => prefetch distance 3).
// mode 0: qkv. q cols -> g_qh fp16 exp + colsums; k/v -> g_k/g_v fp16 head-major.
// mode 1: out[b][dout][n] = qh @ W2_b + bias (B indexed per batch).
#define SLICE 10496              // A 6144 + B 4352
#define STAGE (2 * SLICE)        // 20992
__global__ __launch_bounds__(512, 2) void mma_gemm_kernel(
    const __half* __restrict__ A, const __half* __restrict__ B,
    float* __restrict__ C, const float* __restrict__ bias, int ldb, int mode)
{
    extern __shared__ char smem[];
    uint32_t sb = s2u(smem);
    int tid = threadIdx.x, lane = tid & 31, wid = tid >> 5;
    int m0 = blockIdx.y * 128, n0 = blockIdx.x * 128;
    int wm = (wid >> 2) * 32, wn = (wid & 3) * 32;
    bool loader = (tid < 256);

    if (mode == 1) B += (size_t)(m0 >> 13) * DIM * DIM;   // per-batch W2

    int lt = tid & 255;
    int ar = lt >> 1, ah8 = (lt & 1) * 8;
    int bkr = lt >> 4, bn8 = (lt & 15) * 8;
    const __half* Ag = A + (size_t)(m0 + ar) * DIM + ah8;
    const __half* Bg = B + (size_t)bkr * ldb + n0 + bn8;
    uint32_t dA = sb + ar * 48 + ah8 * 2;
    uint32_t dB = sb + 6144 + bkr * 272 + bn8 * 2;

    uint32_t aAddr[2], bAddr[2];
    #pragma unroll
    for (int mi = 0; mi < 2; mi++)
        aAddr[mi] = sb + (wm + mi * 16 + (lane & 15)) * 48 + (lane >> 4) * 16;
    #pragma unroll
    for (int pi = 0; pi < 2; pi++)
        bAddr[pi] = sb + 6144 + (lane & 15) * 272 +
                    (wn + pi * 16 + (lane >> 4) * 8) * 2;

    float d[2][4][4];
    #pragma unroll
    for (int mi = 0; mi < 2; mi++)
        #pragma unroll
        for (int ni = 0; ni < 4; ni++)
            #pragma unroll
            for (int r = 0; r < 4; r++) d[mi][ni][r] = 0.f;

    if (loader) {
        #pragma unroll
        for (int p = 0; p < 3; p++) {
            #pragma unroll
            for (int s = 0; s < 2; s++) {
                uint32_t so = p * STAGE + s * SLICE;
                int ks = p * 2 + s;
                CP16(dA + so, Ag + ks * 16);
                CP16(dB + so, Bg + (size_t)ks * 16 * ldb);
            }
            CPCOMMIT();
        }
    }

    for (int kk = 0; kk < 16; kk++) {
        if (loader) CPWAIT2();
        __syncthreads();
        if (loader) {
            if (kk + 3 < 16) {
                #pragma unroll
                for (int s = 0; s < 2; s++) {
                    uint32_t so = ((kk + 3) & 3) * STAGE + s * SLICE;
                    int ks = (kk + 3) * 2 + s;
                    CP16(dA + so, Ag + ks * 16);
                    CP16(dB + so, Bg + (size_t)ks * 16 * ldb);
                }
            }
            CPCOMMIT();
        }

        #pragma unroll
        for (int s = 0; s < 2; s++) {
            uint32_t so = (kk & 3) * STAGE + s * SLICE;
            uint32_t ah[2][4], bh[2][4];
            #pragma unroll
            for (int mi = 0; mi < 2; mi++)
                LDSM_X4(ah[mi], aAddr[mi] + so);
            #pragma unroll
            for (int pi = 0; pi < 2; pi++)
                LDSM_X4T(bh[pi], bAddr[pi] + so);
            #pragma unroll
            for (int mi = 0; mi < 2; mi++)
                #pragma unroll
                for (int ni = 0; ni < 4; ni++)
                    MMA(d[mi][ni], ah[mi], &bh[ni >> 1][(ni & 1) * 2]);
        }
    }

    if (mode == 0) {
        int region = n0 >> 9;                  // 0: q, 1: k, 2: v
        if (region == 0) {
            float* qs = (float*)smem;
            __syncthreads();
            if (tid < 128) qs[tid] = 0.f;
            __syncthreads();
            #pragma unroll
            for (int mi = 0; mi < 2; mi++) {
                int r0 = m0 + wm + mi * 16 + (lane >> 2);
                #pragma unroll
                for (int ni = 0; ni < 4; ni++) {
                    int cl = wn + ni * 8 + (lane & 3) * 2;
                    float v0 = __expf(d[mi][ni][0] * SCALE_Q);
                    float v1 = __expf(d[mi][ni][1] * SCALE_Q);
                    float v2 = __expf(d[mi][ni][2] * SCALE_Q);
                    float v3 = __expf(d[mi][ni][3] * SCALE_Q);
                    atomicAdd(&qs[cl],     v0 + v2);
                    atomicAdd(&qs[cl + 1], v1 + v3);
                    *(__half2*)&g_qh[(size_t)r0 * 512 + n0 + cl] =
                        __floats2half2_rn(v0, v1);
                    *(__half2*)&g_qh[(size_t)(r0 + 8) * 512 + n0 + cl] =
                        __floats2half2_rn(v2, v3);
                }
            }
            __syncthreads();
            if (tid < 128)
                atomicAdd(&g_qsum[(m0 >> 13) * DIM + n0 + tid], qs[tid]);
        } else {
            __half* dstbuf = (region == 1) ? g_k : g_v;
            int colbase = n0 & 511;
            #pragma unroll
            for (int mi = 0; mi < 2; mi++) {
                int r0 = m0 + wm + mi * 16 + (lane >> 2);
                int b = r0 >> 13, n = r0 & (SEQ - 1);
                #pragma unroll
                for (int ni = 0; ni < 4; ni++) {
                    int col = colbase + wn + ni * 8 + (lane & 3) * 2;
                    int h = col >> 6, dd = col & 63;
                    size_t base = ((size_t)(b * HEADS + h) * SEQ + n) * 64 + dd;
                    *(__half2*)&dstbuf[base] =
                        __floats2half2_rn(d[mi][ni][0], d[mi][ni][1]);
                    *(__half2*)&dstbuf[base + 8 * 64] =
                        __floats2half2_rn(d[mi][ni][2], d[mi][ni][3]);
                }
            }
        }
    } else {
        __syncthreads();
        float* st = (float*)smem;             // [128][PADT]
        #pragma unroll
        for (int mi = 0; mi < 2; mi++) {
            int r0 = wm + mi * 16 + (lane >> 2);
            #pragma unroll
            for (int ni = 0; ni < 4; ni++) {
                int c0 = wn + ni * 8 + (lane & 3) * 2;
                st[r0 * PADT + c0]           = d[mi][ni][0];
                st[r0 * PADT + c0 + 1]       = d[mi][ni][1];
                st[(r0 + 8) * PADT + c0]     = d[mi][ni][2];
                st[(r0 + 8) * PADT + c0 + 1] = d[mi][ni][3];
            }
        }
        __syncthreads();
        int b = m0 >> 13, nn0 = m0 & (SEQ - 1);
        float* dst = C + (size_t)b * DIM * SEQ + (size_t)n0 * SEQ + nn0;
        for (int idx = tid; idx < 16384; idx += 512) {
            int r = idx >> 7;
            int c = idx & 127;
            dst[(size_t)r * SEQ + c] = st[c * PADT + r] + bias[n0 + r];
        }
    }
}

// ---------------- ctx = softmax_d(k)^T @ v per (b,h) on tensor cores --------
#define TOKCH 1024
#define SUBT  128
#define KTP   72                 // padded row stride in halfs (144B)
__global__ __launch_bounds__(256, 3) void ctx_mma_kernel()
{
    __shared__ __half kt[SUBT * KTP];
    __shared__ __half vt[SUBT * KTP];
    int tid = threadIdx.x, lane = tid & 31, wid = tid >> 5;
    int bh = blockIdx.y;
    int tok0 = blockIdx.x * TOKCH;
    const __half* kbase = g_k + (size_t)bh * SEQ * 64;
    const __half* vbase = g_v + (size_t)bh * SEQ * 64;

    int wm = (wid & 3) * 16, wn = (wid >> 2) * 32;
    int l7 = lane & 7, sel = lane >> 3;
    uint32_t aBase = s2u(kt) + (uint32_t)((((sel >> 1) * 8) + l7) * KTP + wm + (sel & 1) * 8) * 2;
    uint32_t bBase[2];
    #pragma unroll
    for (int pi = 0; pi < 2; pi++)
        bBase[pi] = s2u(vt) + (uint32_t)((lane & 15) * KTP + wn + pi * 16 +
                                         (lane >> 4) * 8) * 2;

    float acc[4][4] = {};
    int t = tid >> 1, h4 = tid & 1;

    for (int st0 = 0; st0 < TOKCH; st0 += SUBT) {
        const uint4* kr4 = (const uint4*)(kbase + (size_t)(tok0 + st0 + t) * 64 + h4 * 32);
        uint4 kr[4];
        #pragma unroll
        for (int i = 0; i < 4; i++) kr[i] = kr4[i];
        float e[32];
        float s = 0.f;
        #pragma unroll
        for (int i = 0; i < 4; i++) {
            const __half2* hp = (const __half2*)&kr[i];
            #pragma unroll
            for (int j = 0; j < 4; j++) {
                float2 f = __half22float2(hp[j]);
                float e0 = __expf(f.x), e1 = __expf(f.y);
                e[i * 8 + j * 2] = e0;
                e[i * 8 + j * 2 + 1] = e1;
                s += e0 + e1;
            }
        }
        s += __shfl_xor_sync(0xffffffffu, s, 1);
        float inv = 1.f / s;
        #pragma unroll
        for (int i = 0; i < 4; i++) {
            uint4 kw;
            __half2* op = (__half2*)&kw;
            #pragma unroll
            for (int j = 0; j < 4; j++)
                op[j] = __floats2half2_rn(e[i * 8 + j * 2] * inv,
                                          e[i * 8 + j * 2 + 1] * inv);
            *(uint4*)&kt[t * KTP + h4 * 32 + i * 8] = kw;
        }
        const uint4* vr4 = (const uint4*)(vbase + (size_t)(tok0 + st0 + t) * 64 + h4 * 32);
        #pragma unroll
        for (int i = 0; i < 4; i++)
            *(uint4*)&vt[t * KTP + h4 * 32 + i * 8] = vr4[i];
        __syncthreads();

        #pragma unroll
        for (int k16 = 0; k16 < SUBT; k16 += 16) {
            uint32_t a[4];
            LDSM_X4T(a, aBase + (uint32_t)k16 * (KTP * 2));
            #pragma unroll
            for (int pi = 0; pi < 2; pi++) {
                uint32_t bb[4];
                LDSM_X4T(bb, bBase[pi] + (uint32_t)k16 * (KTP * 2));
                MMA(acc[pi * 2],     a, &bb[0]);
                MMA(acc[pi * 2 + 1], a, &bb[2]);
            }
        }
        __syncthreads();
    }

    float* cb = g_ctx + (size_t)bh * 4096;
    int r = wm + (lane >> 2);
    #pragma unroll
    for (int ni = 0; ni < 4; ni++) {
        int c = wn + ni * 8 + (lane & 3) * 2;
        atomicAdd(&cb[r * 64 + c],           acc[ni][0]);
        atomicAdd(&cb[r * 64 + c + 1],       acc[ni][1]);
        atomicAdd(&cb[(r + 8) * 64 + c],     acc[ni][2]);
        atomicAdd(&cb[(r + 8) * 64 + c + 1], acc[ni][3]);
    }
}

// ---------------- W2_b = vstack_h( diag(rq_h) * (ctx_bh @ w_out_h) ) --------
__global__ __launch_bounds__(256) void w2_kernel(const float* __restrict__ w_out)
{
    __shared__ float cs[64][65];
    __shared__ float ws[64][128];
    int tid = threadIdx.x;
    int jc = blockIdx.x;
    int bh = blockIdx.y;
    int b = bh >> 3, h = bh & 7;

    const float* csrc = g_ctx + (size_t)bh * 4096;
    for (int i = tid; i < 4096; i += 256) cs[i >> 6][i & 63] = csrc[i];
    for (int i = tid; i < 64 * 128; i += 256) {
        int e = i >> 7, j = i & 127;
        ws[e][j] = w_out[(size_t)(h * 64 + e) * DIM + jc * 128 + j];
    }
    __syncthreads();

    int dd = tid >> 2, j0 = (tid & 3) * 32;
    float rq = 1.f / g_qsum[b * DIM + h * 64 + dd];
    float acc[32] = {};
    #pragma unroll 8
    for (int e = 0; e < 64; e++) {
        float a = cs[dd][e];
        #pragma unroll
        for (int j = 0; j < 32; j++) acc[j] += a * ws[e][j0 + j];
    }
    __half* dst = g_w2 + ((size_t)b * DIM + h * 64 + dd) * DIM + jc * 128 + j0;
    #pragma unroll
    for (int j = 0; j < 32; j += 2)
        *(__half2*)&dst[j] = __floats2half2_rn(acc[j] * rq, acc[j + 1] * rq);
}

// ---------------- launch ------------------------------------------------------
extern "C" void kernel_launch(void* const* d_in, const int* in_sizes, int n_in,
                              void* d_out, int out_size)
{
    const float* x     = (const float*)d_in[0];
    const float* ln_w  = (const float*)d_in[1];
    const float* ln_b  = (const float*)d_in[2];
    const float* w_qkv = (const float*)d_in[3];
    const float* w_out = (const float*)d_in[4];
    const float* b_out = (const float*)d_in[5];
    float* out = (float*)d_out;

    __half *p_a, *p_wq, *p_qh, *p_w2;
    cudaGetSymbolAddress((void**)&p_a, g_a);
    cudaGetSymbolAddress((void**)&p_wq, g_wq);
    cudaGetSymbolAddress((void**)&p_qh, g_qh);
    cudaGetSymbolAddress((void**)&p_w2, g_w2);

    const int LN_SMEM   = 512 * 33 * 2;      // 33792 (fp16 staging)
    const int GEMM_SMEM = 4 * STAGE;         // 83968 >= epilogue 68096
    cudaFuncSetAttribute(ln_kernel, cudaFuncAttributeMaxDynamicSharedMemorySize, LN_SMEM);
    cudaFuncSetAttribute(mma_gemm_kernel, cudaFuncAttributeMaxDynamicSharedMemorySize, GEMM_SMEM);

    wconv_kernel<<<768, 256>>>(w_qkv);
    ln_kernel<<<NTOK / 32, 256, LN_SMEM>>>(x, ln_w, ln_b);
    mma_gemm_kernel<<<dim3(QKVW / 128, MTILES), 512, GEMM_SMEM>>>(
        p_a, p_wq, nullptr, nullptr, QKVW, 0);
    ctx_mma_kernel<<<dim3(SEQ / TOKCH, BATCH * HEADS), 256>>>();
    w2_kernel<<<dim3(4, 32), 256>>>(w_out);
    mma_gemm_kernel<<<dim3(DIM / 128, MTILES), 512, GEMM_SMEM>>>(
        p_qh, p_w2, out, b_out, DIM, 1);
}